// round 1
// baseline (speedup 1.0000x reference)
#include <cuda_runtime.h>
#include <math.h>

#define T_   4096
#define D_   2048
#define H_   16
#define HD_  128
#define TD3  6144   // 3*D

// ---------------- scratch (no allocations allowed) ----------------
__device__ float g_qkv[(size_t)T_ * TD3];   // ~100 MB: [q | k | v] per row
__device__ float g_ao [(size_t)T_ * D_];    // ~33 MB attention output (T, D)

// =================================================================
// Generic SGEMM: C[M,N] = A[M,K] @ B[K,N], row-major fp32.
// 64x64 block tile, BK=16, 256 threads, 4x4 register micro-tile.
// M,N,K all multiples of 64/16 here -> no bounds checks.
// =================================================================
__global__ __launch_bounds__(256) void sgemm64(
    const float* __restrict__ A, const float* __restrict__ B,
    float* __restrict__ C, int M, int N, int K)
{
    __shared__ float As[16][64];   // A tile, transposed: As[k][m]
    __shared__ float Bs[16][64];   // B tile: Bs[k][n]

    const int tid = threadIdx.x;
    const int tx = tid & 15;       // n micro index
    const int ty = tid >> 4;       // m micro index
    const int m0 = blockIdx.y * 64;
    const int n0 = blockIdx.x * 64;

    float acc[4][4] = {};

    for (int k0 = 0; k0 < K; k0 += 16) {
        // --- load A tile (64 x 16), store transposed ---
        {
            int row = tid >> 2;            // 0..63
            int cs  = (tid & 3) * 4;       // 0,4,8,12
            float4 a = *(const float4*)&A[(size_t)(m0 + row) * K + k0 + cs];
            As[cs + 0][row] = a.x;
            As[cs + 1][row] = a.y;
            As[cs + 2][row] = a.z;
            As[cs + 3][row] = a.w;
        }
        // --- load B tile (16 x 64) ---
        {
            int br = tid >> 4;             // 0..15
            int bc = (tid & 15) * 4;       // 0..60
            *(float4*)&Bs[br][bc] =
                *(const float4*)&B[(size_t)(k0 + br) * N + n0 + bc];
        }
        __syncthreads();

        #pragma unroll
        for (int k = 0; k < 16; k++) {
            float4 a4 = *(float4*)&As[k][ty * 4];
            float4 b4 = *(float4*)&Bs[k][tx * 4];
            float av[4] = {a4.x, a4.y, a4.z, a4.w};
            float bv[4] = {b4.x, b4.y, b4.z, b4.w};
            #pragma unroll
            for (int i = 0; i < 4; i++)
                #pragma unroll
                for (int j = 0; j < 4; j++)
                    acc[i][j] += av[i] * bv[j];
        }
        __syncthreads();
    }

    #pragma unroll
    for (int i = 0; i < 4; i++) {
        float4 o = make_float4(acc[i][0], acc[i][1], acc[i][2], acc[i][3]);
        *(float4*)&C[(size_t)(m0 + ty * 4 + i) * N + n0 + tx * 4] = o;
    }
}

// =================================================================
// L2-normalize q and k segments of g_qkv in-place.
// One warp per (t, h, q-or-k) segment of HD=128 floats.
// total segments = T*H*2 = 131072
// =================================================================
__global__ __launch_bounds__(256) void l2norm_qk()
{
    int gw = blockIdx.x * 8 + (threadIdx.x >> 5);   // global warp id
    int l  = threadIdx.x & 31;

    int which = gw >> 16;           // 0 = q, 1 = k   (T*H = 65536)
    int rem   = gw & 65535;
    int t = rem >> 4;
    int h = rem & 15;

    float* p = g_qkv + (size_t)t * TD3 + which * D_ + h * HD_ + l * 4;
    float4 v = *(float4*)p;
    float ss = v.x * v.x + v.y * v.y + v.z * v.z + v.w * v.w;
    #pragma unroll
    for (int o = 16; o; o >>= 1) ss += __shfl_xor_sync(0xffffffffu, ss, o);

    float inv = 1.0f / fmaxf(sqrtf(ss), 1e-12f);
    v.x *= inv; v.y *= inv; v.z *= inv; v.w *= inv;
    *(float4*)p = v;
}

// =================================================================
// Fused flash attention (fp32, online softmax).
// grid = (T/64, H); block = 256 (8 warps).
// Warp w owns S rows 8w..8w+7: computes QK^T, softmax, P@V, O acc.
// Smem: Qs[64][128], Ks[64][132] (padded), Vs[64][128], Ps[64][64]
// =================================================================
#define ATTN_SMEM_FLOATS (64*128 + 64*132 + 64*128 + 64*64)
#define ATTN_SMEM_BYTES  (ATTN_SMEM_FLOATS * 4)

__global__ __launch_bounds__(256) void attn_kernel(const float* __restrict__ mask)
{
    extern __shared__ float sm[];
    float* Qs = sm;                       // [64][128]
    float* Ks = Qs + 64 * 128;            // [64][132]  (pad 4 -> conflict-free lane reads)
    float* Vs = Ks + 64 * 132;            // [64][128]
    float* Ps = Vs + 64 * 128;            // [64][64]

    const int tid = threadIdx.x;
    const int w = tid >> 5;               // warp 0..7
    const int l = tid & 31;               // lane
    const int q0 = blockIdx.x * 64;       // query block start
    const int h  = blockIdx.y;            // head
    const float scale = 0.08838834764831845f;   // 128^-0.5

    // ---- load Q tile (64 x 128) ----
    #pragma unroll
    for (int it = 0; it < 8; it++) {
        int f4 = it * 256 + tid;
        int r = f4 >> 5;
        int c = (f4 & 31) * 4;
        *(float4*)&Qs[r * 128 + c] =
            *(const float4*)&g_qkv[(size_t)(q0 + r) * TD3 + h * HD_ + c];
    }

    float acc[8][4];
    float mrow[8], lrow[8];
    #pragma unroll
    for (int q = 0; q < 8; q++) {
        mrow[q] = -INFINITY;
        lrow[q] = 0.0f;
        acc[q][0] = acc[q][1] = acc[q][2] = acc[q][3] = 0.0f;
    }

    for (int kt = 0; kt < T_; kt += 64) {
        __syncthreads();   // previous tile fully consumed before overwrite
        // ---- load K, V tiles (64 x 128 each) ----
        #pragma unroll
        for (int it = 0; it < 8; it++) {
            int f4 = it * 256 + tid;
            int r = f4 >> 5;
            int c = (f4 & 31) * 4;
            *(float4*)&Ks[r * 132 + c] =
                *(const float4*)&g_qkv[(size_t)(kt + r) * TD3 + D_ + h * HD_ + c];
            *(float4*)&Vs[r * 128 + c] =
                *(const float4*)&g_qkv[(size_t)(kt + r) * TD3 + 2 * D_ + h * HD_ + c];
        }
        __syncthreads();

        // ---- S = Q K^T for this warp's 8 rows; lane l handles keys l, l+32 ----
        float s0[8] = {}, s1[8] = {};
        const float* Krow0 = &Ks[l * 132];
        const float* Krow1 = &Ks[(l + 32) * 132];
        #pragma unroll 4
        for (int d4 = 0; d4 < 32; d4++) {
            float4 k0 = *(const float4*)&Krow0[d4 * 4];
            float4 k1 = *(const float4*)&Krow1[d4 * 4];
            #pragma unroll
            for (int q = 0; q < 8; q++) {
                float4 qv = *(const float4*)&Qs[(w * 8 + q) * 128 + d4 * 4];
                s0[q] += qv.x * k0.x + qv.y * k0.y + qv.z * k0.z + qv.w * k0.w;
                s1[q] += qv.x * k1.x + qv.y * k1.y + qv.z * k1.z + qv.w * k1.w;
            }
        }

        // ---- online softmax per row (warp-local), write P ----
        #pragma unroll
        for (int q = 0; q < 8; q++) {
            int row = w * 8 + q;
            int tg  = q0 + row;
            float v0 = s0[q] * scale + mask[(size_t)tg * T_ + kt + l];
            float v1 = s1[q] * scale + mask[(size_t)tg * T_ + kt + l + 32];
            float tmax = fmaxf(v0, v1);
            #pragma unroll
            for (int o = 16; o; o >>= 1)
                tmax = fmaxf(tmax, __shfl_xor_sync(0xffffffffu, tmax, o));
            float mnew = fmaxf(mrow[q], tmax);
            float p0 = __expf(v0 - mnew);
            float p1 = __expf(v1 - mnew);
            float ps = p0 + p1;
            #pragma unroll
            for (int o = 16; o; o >>= 1)
                ps += __shfl_xor_sync(0xffffffffu, ps, o);
            float corr = __expf(mrow[q] - mnew);
            lrow[q] = lrow[q] * corr + ps;
            mrow[q] = mnew;
            acc[q][0] *= corr; acc[q][1] *= corr;
            acc[q][2] *= corr; acc[q][3] *= corr;
            Ps[row * 64 + l]      = p0;
            Ps[row * 64 + l + 32] = p1;
        }

        // ---- O += P @ V (warp-local rows; lane l owns dims 4l..4l+3) ----
        #pragma unroll 8
        for (int k = 0; k < 64; k++) {
            float4 v = *(const float4*)&Vs[k * 128 + l * 4];
            #pragma unroll
            for (int q = 0; q < 8; q++) {
                float p = Ps[(w * 8 + q) * 64 + k];   // warp broadcast
                acc[q][0] += p * v.x;
                acc[q][1] += p * v.y;
                acc[q][2] += p * v.z;
                acc[q][3] += p * v.w;
            }
        }
    }

    // ---- epilogue: normalize and write (T, H*HD) layout ----
    #pragma unroll
    for (int q = 0; q < 8; q++) {
        int row = w * 8 + q;
        float inv = 1.0f / lrow[q];
        float4 o = make_float4(acc[q][0] * inv, acc[q][1] * inv,
                               acc[q][2] * inv, acc[q][3] * inv);
        *(float4*)&g_ao[(size_t)(q0 + row) * D_ + h * HD_ + l * 4] = o;
    }
}

// =================================================================
// Launch
// =================================================================
extern "C" void kernel_launch(void* const* d_in, const int* in_sizes, int n_in,
                              void* d_out, int out_size)
{
    const float* x    = (const float*)d_in[0];
    const float* mask = (const float*)d_in[1];
    const float* Wqkv = (const float*)d_in[2];
    const float* Wout = (const float*)d_in[3];
    float* out = (float*)d_out;

    float *qkv, *ao;
    cudaGetSymbolAddress((void**)&qkv, g_qkv);
    cudaGetSymbolAddress((void**)&ao,  g_ao);

    cudaFuncSetAttribute(attn_kernel,
                         cudaFuncAttributeMaxDynamicSharedMemorySize,
                         ATTN_SMEM_BYTES);

    // 1) qkv = x @ W_qkv
    dim3 g1(TD3 / 64, T_ / 64);
    sgemm64<<<g1, 256>>>(x, Wqkv, qkv, T_, TD3, D_);

    // 2) L2-normalize q, k per (t, h)
    l2norm_qk<<<(T_ * H_ * 2) / 8, 256>>>();

    // 3) fused attention -> g_ao (already in (T, D) layout)
    attn_kernel<<<dim3(T_ / 64, H_), 256, ATTN_SMEM_BYTES>>>(mask);

    // 4) out = ao @ W_out
    dim3 g2(D_ / 64, T_ / 64);
    sgemm64<<<g2, 256>>>(ao, Wout, out, T_, D_, D_);
}

// round 4
// speedup vs baseline: 1.4225x; 1.4225x over previous
#include <cuda_runtime.h>
#include <cuda_bf16.h>
#include <math.h>
#include <stdint.h>

#define T_   4096
#define D_   2048
#define H_   16
#define HD_  128
#define TD3  6144   // 3*D

// ---------------- scratch (no allocations allowed) ----------------
__device__ float g_qkv[(size_t)T_ * TD3];   // [q | k | v] per row, fp32
__device__ float g_ao [(size_t)T_ * D_];    // attention output (T, D) fp32

// split-precision bf16 buffers
__device__ __nv_bfloat16 g_xh[(size_t)T_ * D_];
__device__ __nv_bfloat16 g_xl[(size_t)T_ * D_];
__device__ __nv_bfloat16 g_wqh[(size_t)TD3 * D_];   // Wqkv^T  [6144][2048]
__device__ __nv_bfloat16 g_wql[(size_t)TD3 * D_];
__device__ __nv_bfloat16 g_woh[(size_t)D_ * D_];    // Wout^T  [2048][2048]
__device__ __nv_bfloat16 g_wol[(size_t)D_ * D_];
__device__ __nv_bfloat16 g_aoh[(size_t)T_ * D_];
__device__ __nv_bfloat16 g_aol[(size_t)T_ * D_];

// =================================================================
// PTX helpers (portable: ldmatrix / mma.sync / cp.async)
// =================================================================
__device__ __forceinline__ uint32_t smem_u32(const void* p) {
    uint32_t a;
    asm("{ .reg .u64 t; cvta.to.shared.u64 t, %1; cvt.u32.u64 %0, t; }"
        : "=r"(a) : "l"(p));
    return a;
}
__device__ __forceinline__ void ldsm4(uint32_t* r, uint32_t a) {
    asm volatile("ldmatrix.sync.aligned.m8n8.x4.shared.b16 {%0,%1,%2,%3}, [%4];"
                 : "=r"(r[0]), "=r"(r[1]), "=r"(r[2]), "=r"(r[3]) : "r"(a));
}
__device__ __forceinline__ void mma16816(float* c, const uint32_t* a,
                                         uint32_t b0, uint32_t b1) {
    asm volatile(
        "mma.sync.aligned.m16n8k16.row.col.f32.bf16.bf16.f32 "
        "{%0,%1,%2,%3}, {%4,%5,%6,%7}, {%8,%9}, {%0,%1,%2,%3};"
        : "+f"(c[0]), "+f"(c[1]), "+f"(c[2]), "+f"(c[3])
        : "r"(a[0]), "r"(a[1]), "r"(a[2]), "r"(a[3]), "r"(b0), "r"(b1));
}
#define CP_ASYNC16(sa, ga) \
    asm volatile("cp.async.cg.shared.global [%0], [%1], 16;" :: "r"(sa), "l"(ga))
#define CP_COMMIT() asm volatile("cp.async.commit_group;" ::: "memory")
#define CP_WAIT0()  asm volatile("cp.async.wait_group 0;" ::: "memory")

// =================================================================
// Split / transpose kernels
// =================================================================
__global__ __launch_bounds__(256) void split_hl(const float4* __restrict__ src,
                                                uint2* __restrict__ hi,
                                                uint2* __restrict__ lo)
{
    size_t i = (size_t)blockIdx.x * 256 + threadIdx.x;
    float4 v = src[i];
    __nv_bfloat162 h0 = __floats2bfloat162_rn(v.x, v.y);
    __nv_bfloat162 h1 = __floats2bfloat162_rn(v.z, v.w);
    float rx = v.x - __low2float(h0),  ry = v.y - __high2float(h0);
    float rz = v.z - __low2float(h1),  rw = v.w - __high2float(h1);
    __nv_bfloat162 l0 = __floats2bfloat162_rn(rx, ry);
    __nv_bfloat162 l1 = __floats2bfloat162_rn(rz, rw);
    uint2 hv, lv;
    hv.x = *reinterpret_cast<unsigned*>(&h0); hv.y = *reinterpret_cast<unsigned*>(&h1);
    lv.x = *reinterpret_cast<unsigned*>(&l0); lv.y = *reinterpret_cast<unsigned*>(&l1);
    hi[i] = hv;
    lo[i] = lv;
}

// src[R][C] fp32  ->  out[C][R] bf16 hi/lo (transpose + split)
__global__ __launch_bounds__(256) void tsplit(const float* __restrict__ src,
                                              __nv_bfloat16* __restrict__ dh,
                                              __nv_bfloat16* __restrict__ dl,
                                              int R, int C)
{
    __shared__ float tile[32][33];
    int tx = threadIdx.x, ty = threadIdx.y;
    int x0 = blockIdx.x * 32, y0 = blockIdx.y * 32;
    #pragma unroll
    for (int j = 0; j < 4; j++)
        tile[ty + j * 8][tx] = src[(size_t)(y0 + ty + j * 8) * C + x0 + tx];
    __syncthreads();
    #pragma unroll
    for (int j = 0; j < 4; j++) {
        float v = tile[tx][ty + j * 8];
        __nv_bfloat16 h = __float2bfloat16(v);
        __nv_bfloat16 l = __float2bfloat16(v - __bfloat162float(h));
        size_t o = (size_t)(x0 + ty + j * 8) * R + y0 + tx;
        dh[o] = h;
        dl[o] = l;
    }
}

// =================================================================
// Split-bf16 mma.sync GEMM: C[M,N] = A[M,K] @ Bt[N,K]^T (fp32 out)
// CTA tile 128x128, BK=32, 256 thr (8 warps, 2x4), warp tile 64x32.
// Double-buffered cp.async smem; padded rows (40 bf16 = 80B).
// =================================================================
#define BM 128
#define BN 128
#define BKC 32
#define ROWB 80                       // bytes per padded smem row (32 bf16 + 8 pad)
#define TILE_B (128 * ROWB)           // 10240 B per operand tile
#define STAGE_B (4 * TILE_B)          // Ah|Al|Bh|Bl = 40960 B
#define GEMM_SMEM (2 * STAGE_B)       // 81920 B

__device__ __forceinline__ void cpa_tile(uint32_t sbase,
                                         const __nv_bfloat16* __restrict__ g,
                                         int row0, int k0, int K, int tid)
{
    #pragma unroll
    for (int i = 0; i < 2; i++) {
        int ch = tid + i * 256;           // 0..511
        int r  = ch >> 2;                 // 0..127
        int cc = (ch & 3) * 8;            // bf16 col 0,8,16,24
        uint32_t sa = sbase + r * ROWB + cc * 2;
        const void* ga = g + (size_t)(row0 + r) * K + k0 + cc;
        CP_ASYNC16(sa, ga);
    }
}

__global__ __launch_bounds__(256) void gemm_split(
    const __nv_bfloat16* __restrict__ Ah, const __nv_bfloat16* __restrict__ Al,
    const __nv_bfloat16* __restrict__ Bh, const __nv_bfloat16* __restrict__ Bl,
    float* __restrict__ C, int M, int N, int K)
{
    extern __shared__ char smem[];
    uint32_t sb = smem_u32(smem);
    const int tid  = threadIdx.x;
    const int lane = tid & 31;
    const int wid  = tid >> 5;
    const int wm   = wid >> 2;            // 0..1
    const int wn   = wid & 3;             // 0..3
    const int m0 = blockIdx.y * BM;
    const int n0 = blockIdx.x * BN;
    const int NC = K / BKC;

    float acc[4][4][4] = {};

    // prologue: chunk 0 -> buffer 0
    cpa_tile(sb,              Ah, m0, 0, K, tid);
    cpa_tile(sb + TILE_B,     Al, m0, 0, K, tid);
    cpa_tile(sb + 2 * TILE_B, Bh, n0, 0, K, tid);
    cpa_tile(sb + 3 * TILE_B, Bl, n0, 0, K, tid);
    CP_COMMIT();
    CP_WAIT0();
    __syncthreads();

    const int lm  = lane & 15;
    const int lk8 = (lane >> 4) * 8;      // 0 or 8 (bf16)

    for (int c = 0; c < NC; c++) {
        uint32_t sbuf = sb + (c & 1) * STAGE_B;
        if (c + 1 < NC) {
            uint32_t snext = sb + ((c + 1) & 1) * STAGE_B;
            int k0 = (c + 1) * BKC;
            cpa_tile(snext,              Ah, m0, k0, K, tid);
            cpa_tile(snext + TILE_B,     Al, m0, k0, K, tid);
            cpa_tile(snext + 2 * TILE_B, Bh, n0, k0, K, tid);
            cpa_tile(snext + 3 * TILE_B, Bl, n0, k0, K, tid);
            CP_COMMIT();
        }

        uint32_t sA  = sbuf;
        uint32_t sAl = sbuf + TILE_B;
        uint32_t sB  = sbuf + 2 * TILE_B;
        uint32_t sBl = sbuf + 3 * TILE_B;

        #pragma unroll
        for (int ks = 0; ks < 2; ks++) {
            uint32_t kb = (ks * 16 + lk8) * 2;     // byte offset of this lane's k
            uint32_t ah[4][4], al[4][4], bh[2][4], bl[2][4];
            #pragma unroll
            for (int mf = 0; mf < 4; mf++) {
                uint32_t ro = (wm * 64 + mf * 16 + lm) * ROWB + kb;
                ldsm4(ah[mf], sA + ro);
                ldsm4(al[mf], sAl + ro);
            }
            #pragma unroll
            for (int nf2 = 0; nf2 < 2; nf2++) {
                uint32_t ro = (wn * 32 + nf2 * 16 + lm) * ROWB + kb;
                ldsm4(bh[nf2], sB + ro);
                ldsm4(bl[nf2], sBl + ro);
            }
            #pragma unroll
            for (int mf = 0; mf < 4; mf++)
                #pragma unroll
                for (int nf = 0; nf < 4; nf++) {
                    uint32_t b0h = bh[nf >> 1][nf & 1];
                    uint32_t b1h = bh[nf >> 1][(nf & 1) + 2];
                    uint32_t b0l = bl[nf >> 1][nf & 1];
                    uint32_t b1l = bl[nf >> 1][(nf & 1) + 2];
                    mma16816(acc[mf][nf], ah[mf], b0h, b1h);   // hi*hi
                    mma16816(acc[mf][nf], ah[mf], b0l, b1l);   // hi*lo
                    mma16816(acc[mf][nf], al[mf], b0h, b1h);   // lo*hi
                }
        }

        if (c + 1 < NC) {
            CP_WAIT0();
            __syncthreads();
        }
    }

    // epilogue: frag -> gmem fp32
    int mbase = m0 + wm * 64;
    int nbase = n0 + wn * 32;
    #pragma unroll
    for (int mf = 0; mf < 4; mf++)
        #pragma unroll
        for (int nf = 0; nf < 4; nf++) {
            int r0 = mbase + mf * 16 + (lane >> 2);
            int c0 = nbase + nf * 8 + (lane & 3) * 2;
            *(float2*)&C[(size_t)r0 * N + c0] =
                make_float2(acc[mf][nf][0], acc[mf][nf][1]);
            *(float2*)&C[(size_t)(r0 + 8) * N + c0] =
                make_float2(acc[mf][nf][2], acc[mf][nf][3]);
        }
}

// =================================================================
// L2-normalize q and k segments of g_qkv in-place (unchanged, passing).
// =================================================================
__global__ __launch_bounds__(256) void l2norm_qk()
{
    int gw = blockIdx.x * 8 + (threadIdx.x >> 5);
    int l  = threadIdx.x & 31;
    int which = gw >> 16;
    int rem   = gw & 65535;
    int t = rem >> 4;
    int h = rem & 15;

    float* p = g_qkv + (size_t)t * TD3 + which * D_ + h * HD_ + l * 4;
    float4 v = *(float4*)p;
    float ss = v.x * v.x + v.y * v.y + v.z * v.z + v.w * v.w;
    #pragma unroll
    for (int o = 16; o; o >>= 1) ss += __shfl_xor_sync(0xffffffffu, ss, o);
    float inv = 1.0f / fmaxf(sqrtf(ss), 1e-12f);
    v.x *= inv; v.y *= inv; v.z *= inv; v.w *= inv;
    *(float4*)p = v;
}

// =================================================================
// Fused flash attention (fp32, online softmax) — unchanged, passing.
// =================================================================
#define ATTN_SMEM_FLOATS (64*128 + 64*132 + 64*128 + 64*64)
#define ATTN_SMEM_BYTES  (ATTN_SMEM_FLOATS * 4)

__global__ __launch_bounds__(256) void attn_kernel(const float* __restrict__ mask)
{
    extern __shared__ float sm[];
    float* Qs = sm;
    float* Ks = Qs + 64 * 128;
    float* Vs = Ks + 64 * 132;
    float* Ps = Vs + 64 * 128;

    const int tid = threadIdx.x;
    const int w = tid >> 5;
    const int l = tid & 31;
    const int q0 = blockIdx.x * 64;
    const int h  = blockIdx.y;
    const float scale = 0.08838834764831845f;

    #pragma unroll
    for (int it = 0; it < 8; it++) {
        int f4 = it * 256 + tid;
        int r = f4 >> 5;
        int c = (f4 & 31) * 4;
        *(float4*)&Qs[r * 128 + c] =
            *(const float4*)&g_qkv[(size_t)(q0 + r) * TD3 + h * HD_ + c];
    }

    float acc[8][4];
    float mrow[8], lrow[8];
    #pragma unroll
    for (int q = 0; q < 8; q++) {
        mrow[q] = -INFINITY;
        lrow[q] = 0.0f;
        acc[q][0] = acc[q][1] = acc[q][2] = acc[q][3] = 0.0f;
    }

    for (int kt = 0; kt < T_; kt += 64) {
        __syncthreads();
        #pragma unroll
        for (int it = 0; it < 8; it++) {
            int f4 = it * 256 + tid;
            int r = f4 >> 5;
            int c = (f4 & 31) * 4;
            *(float4*)&Ks[r * 132 + c] =
                *(const float4*)&g_qkv[(size_t)(kt + r) * TD3 + D_ + h * HD_ + c];
            *(float4*)&Vs[r * 128 + c] =
                *(const float4*)&g_qkv[(size_t)(kt + r) * TD3 + 2 * D_ + h * HD_ + c];
        }
        __syncthreads();

        float s0[8] = {}, s1[8] = {};
        const float* Krow0 = &Ks[l * 132];
        const float* Krow1 = &Ks[(l + 32) * 132];
        #pragma unroll 4
        for (int d4 = 0; d4 < 32; d4++) {
            float4 k0 = *(const float4*)&Krow0[d4 * 4];
            float4 k1 = *(const float4*)&Krow1[d4 * 4];
            #pragma unroll
            for (int q = 0; q < 8; q++) {
                float4 qv = *(const float4*)&Qs[(w * 8 + q) * 128 + d4 * 4];
                s0[q] += qv.x * k0.x + qv.y * k0.y + qv.z * k0.z + qv.w * k0.w;
                s1[q] += qv.x * k1.x + qv.y * k1.y + qv.z * k1.z + qv.w * k1.w;
            }
        }

        #pragma unroll
        for (int q = 0; q < 8; q++) {
            int row = w * 8 + q;
            int tg  = q0 + row;
            float v0 = s0[q] * scale + mask[(size_t)tg * T_ + kt + l];
            float v1 = s1[q] * scale + mask[(size_t)tg * T_ + kt + l + 32];
            float tmax = fmaxf(v0, v1);
            #pragma unroll
            for (int o = 16; o; o >>= 1)
                tmax = fmaxf(tmax, __shfl_xor_sync(0xffffffffu, tmax, o));
            float mnew = fmaxf(mrow[q], tmax);
            float p0 = __expf(v0 - mnew);
            float p1 = __expf(v1 - mnew);
            float ps = p0 + p1;
            #pragma unroll
            for (int o = 16; o; o >>= 1)
                ps += __shfl_xor_sync(0xffffffffu, ps, o);
            float corr = __expf(mrow[q] - mnew);
            lrow[q] = lrow[q] * corr + ps;
            mrow[q] = mnew;
            acc[q][0] *= corr; acc[q][1] *= corr;
            acc[q][2] *= corr; acc[q][3] *= corr;
            Ps[row * 64 + l]      = p0;
            Ps[row * 64 + l + 32] = p1;
        }

        #pragma unroll 8
        for (int k = 0; k < 64; k++) {
            float4 v = *(const float4*)&Vs[k * 128 + l * 4];
            #pragma unroll
            for (int q = 0; q < 8; q++) {
                float p = Ps[(w * 8 + q) * 64 + k];
                acc[q][0] += p * v.x;
                acc[q][1] += p * v.y;
                acc[q][2] += p * v.z;
                acc[q][3] += p * v.w;
            }
        }
    }

    #pragma unroll
    for (int q = 0; q < 8; q++) {
        int row = w * 8 + q;
        float inv = 1.0f / lrow[q];
        float4 o = make_float4(acc[q][0] * inv, acc[q][1] * inv,
                               acc[q][2] * inv, acc[q][3] * inv);
        *(float4*)&g_ao[(size_t)(q0 + row) * D_ + h * HD_ + l * 4] = o;
    }
}

// =================================================================
// Launch
// =================================================================
extern "C" void kernel_launch(void* const* d_in, const int* in_sizes, int n_in,
                              void* d_out, int out_size)
{
    const float* x    = (const float*)d_in[0];
    const float* mask = (const float*)d_in[1];
    const float* Wqkv = (const float*)d_in[2];
    const float* Wout = (const float*)d_in[3];
    float* out = (float*)d_out;

    float *qkv, *ao;
    __nv_bfloat16 *xh, *xl, *wqh, *wql, *woh, *wol, *aoh, *aol;
    cudaGetSymbolAddress((void**)&qkv, g_qkv);
    cudaGetSymbolAddress((void**)&ao,  g_ao);
    cudaGetSymbolAddress((void**)&xh,  g_xh);
    cudaGetSymbolAddress((void**)&xl,  g_xl);
    cudaGetSymbolAddress((void**)&wqh, g_wqh);
    cudaGetSymbolAddress((void**)&wql, g_wql);
    cudaGetSymbolAddress((void**)&woh, g_woh);
    cudaGetSymbolAddress((void**)&wol, g_wol);
    cudaGetSymbolAddress((void**)&aoh, g_aoh);
    cudaGetSymbolAddress((void**)&aol, g_aol);

    cudaFuncSetAttribute(attn_kernel,
                         cudaFuncAttributeMaxDynamicSharedMemorySize, ATTN_SMEM_BYTES);
    cudaFuncSetAttribute(gemm_split,
                         cudaFuncAttributeMaxDynamicSharedMemorySize, GEMM_SMEM);

    // 1) split x and weights (weights transposed to [N][K])
    split_hl<<<(T_ * D_ / 4) / 256, 256>>>((const float4*)x, (uint2*)xh, (uint2*)xl);
    tsplit<<<dim3(TD3 / 32, D_ / 32), dim3(32, 8)>>>(Wqkv, wqh, wql, D_, TD3);
    tsplit<<<dim3(D_ / 32,  D_ / 32), dim3(32, 8)>>>(Wout, woh, wol, D_, D_);

    // 2) qkv = x @ W_qkv   (mma.sync split-bf16)
    gemm_split<<<dim3(TD3 / BN, T_ / BM), 256, GEMM_SMEM>>>(
        xh, xl, wqh, wql, qkv, T_, TD3, D_);

    // 3) L2-normalize q, k
    l2norm_qk<<<(T_ * H_ * 2) / 8, 256>>>();

    // 4) fused attention -> g_ao
    attn_kernel<<<dim3(T_ / 64, H_), 256, ATTN_SMEM_BYTES>>>(mask);

    // 5) out = ao @ W_out  (mma.sync split-bf16)
    split_hl<<<(T_ * D_ / 4) / 256, 256>>>((const float4*)ao, (uint2*)aoh, (uint2*)aol);
    gemm_split<<<dim3(D_ / BN, T_ / BM), 256, GEMM_SMEM>>>(
        aoh, aol, woh, wol, out, T_, D_, D_);
}

// round 5
// speedup vs baseline: 3.1074x; 2.1844x over previous
#include <cuda_runtime.h>
#include <cuda_bf16.h>
#include <math.h>
#include <stdint.h>

#define T_   4096
#define D_   2048
#define H_   16
#define HD_  128
#define TD3  6144   // 3*D

// ---------------- scratch (no allocations allowed) ----------------
__device__ float g_qkv[(size_t)T_ * TD3];   // [q | k | v] per row, fp32
__device__ float g_ao [(size_t)T_ * D_];    // attention output (T, D) fp32

// split-precision bf16 buffers for dense GEMMs
__device__ __nv_bfloat16 g_xh[(size_t)T_ * D_];
__device__ __nv_bfloat16 g_xl[(size_t)T_ * D_];
__device__ __nv_bfloat16 g_wqh[(size_t)TD3 * D_];   // Wqkv^T  [6144][2048]
__device__ __nv_bfloat16 g_wql[(size_t)TD3 * D_];
__device__ __nv_bfloat16 g_woh[(size_t)D_ * D_];    // Wout^T  [2048][2048]
__device__ __nv_bfloat16 g_wol[(size_t)D_ * D_];
__device__ __nv_bfloat16 g_aoh[(size_t)T_ * D_];
__device__ __nv_bfloat16 g_aol[(size_t)T_ * D_];

// attention bf16 operands
__device__ __nv_bfloat16 g_qbh[(size_t)T_ * D_];          // normalized q, bf16
__device__ __nv_bfloat16 g_kbh[(size_t)T_ * D_];          // normalized k, bf16
__device__ __nv_bfloat16 g_vth[(size_t)H_ * HD_ * T_];    // V^T per head, hi
__device__ __nv_bfloat16 g_vtl[(size_t)H_ * HD_ * T_];    // V^T per head, lo

// =================================================================
// PTX helpers (portable: ldmatrix / mma.sync / cp.async)
// =================================================================
__device__ __forceinline__ uint32_t smem_u32(const void* p) {
    uint32_t a;
    asm("{ .reg .u64 t; cvta.to.shared.u64 t, %1; cvt.u32.u64 %0, t; }"
        : "=r"(a) : "l"(p));
    return a;
}
__device__ __forceinline__ void ldsm4(uint32_t* r, uint32_t a) {
    asm volatile("ldmatrix.sync.aligned.m8n8.x4.shared.b16 {%0,%1,%2,%3}, [%4];"
                 : "=r"(r[0]), "=r"(r[1]), "=r"(r[2]), "=r"(r[3]) : "r"(a));
}
__device__ __forceinline__ void mma16816(float* c, const uint32_t* a,
                                         uint32_t b0, uint32_t b1) {
    asm volatile(
        "mma.sync.aligned.m16n8k16.row.col.f32.bf16.bf16.f32 "
        "{%0,%1,%2,%3}, {%4,%5,%6,%7}, {%8,%9}, {%0,%1,%2,%3};"
        : "+f"(c[0]), "+f"(c[1]), "+f"(c[2]), "+f"(c[3])
        : "r"(a[0]), "r"(a[1]), "r"(a[2]), "r"(a[3]), "r"(b0), "r"(b1));
}
#define CP_ASYNC16(sa, ga) \
    asm volatile("cp.async.cg.shared.global [%0], [%1], 16;" :: "r"(sa), "l"(ga))
#define CP_COMMIT() asm volatile("cp.async.commit_group;" ::: "memory")
#define CP_WAIT0()  asm volatile("cp.async.wait_group 0;" ::: "memory")

// =================================================================
// Split / transpose kernels
// =================================================================
__global__ __launch_bounds__(256) void split_hl(const float4* __restrict__ src,
                                                uint2* __restrict__ hi,
                                                uint2* __restrict__ lo)
{
    size_t i = (size_t)blockIdx.x * 256 + threadIdx.x;
    float4 v = src[i];
    __nv_bfloat162 h0 = __floats2bfloat162_rn(v.x, v.y);
    __nv_bfloat162 h1 = __floats2bfloat162_rn(v.z, v.w);
    float rx = v.x - __low2float(h0),  ry = v.y - __high2float(h0);
    float rz = v.z - __low2float(h1),  rw = v.w - __high2float(h1);
    __nv_bfloat162 l0 = __floats2bfloat162_rn(rx, ry);
    __nv_bfloat162 l1 = __floats2bfloat162_rn(rz, rw);
    uint2 hv, lv;
    hv.x = *reinterpret_cast<unsigned*>(&h0); hv.y = *reinterpret_cast<unsigned*>(&h1);
    lv.x = *reinterpret_cast<unsigned*>(&l0); lv.y = *reinterpret_cast<unsigned*>(&l1);
    hi[i] = hv;
    lo[i] = lv;
}

// src[R][C] fp32  ->  out[C][R] bf16 hi/lo (transpose + split)
__global__ __launch_bounds__(256) void tsplit(const float* __restrict__ src,
                                              __nv_bfloat16* __restrict__ dh,
                                              __nv_bfloat16* __restrict__ dl,
                                              int R, int C)
{
    __shared__ float tile[32][33];
    int tx = threadIdx.x, ty = threadIdx.y;
    int x0 = blockIdx.x * 32, y0 = blockIdx.y * 32;
    #pragma unroll
    for (int j = 0; j < 4; j++)
        tile[ty + j * 8][tx] = src[(size_t)(y0 + ty + j * 8) * C + x0 + tx];
    __syncthreads();
    #pragma unroll
    for (int j = 0; j < 4; j++) {
        float v = tile[tx][ty + j * 8];
        __nv_bfloat16 h = __float2bfloat16(v);
        __nv_bfloat16 l = __float2bfloat16(v - __bfloat162float(h));
        size_t o = (size_t)(x0 + ty + j * 8) * R + y0 + tx;
        dh[o] = h;
        dl[o] = l;
    }
}

// V region of g_qkv -> per-head transposed split: g_vt{h,l}[h][d][t]
// grid (T/32, HD/32, H), block (32, 8)
__global__ __launch_bounds__(256) void vtsplit()
{
    __shared__ float tile[32][33];
    int tx = threadIdx.x, ty = threadIdx.y;
    int t0 = blockIdx.x * 32, d0 = blockIdx.y * 32, h = blockIdx.z;
    #pragma unroll
    for (int j = 0; j < 4; j++)
        tile[ty + j * 8][tx] =
            g_qkv[(size_t)(t0 + ty + j * 8) * TD3 + 2 * D_ + h * HD_ + d0 + tx];
    __syncthreads();
    size_t base = (size_t)h * HD_ * T_;
    #pragma unroll
    for (int j = 0; j < 4; j++) {
        float v = tile[tx][ty + j * 8];
        __nv_bfloat16 hh = __float2bfloat16(v);
        __nv_bfloat16 ll = __float2bfloat16(v - __bfloat162float(hh));
        size_t o = base + (size_t)(d0 + ty + j * 8) * T_ + t0 + tx;
        g_vth[o] = hh;
        g_vtl[o] = ll;
    }
}

// =================================================================
// Split-bf16 mma.sync GEMM (unchanged from R4 — passing)
// =================================================================
#define BM 128
#define BN 128
#define BKC 32
#define ROWB 80
#define TILE_B (128 * ROWB)
#define STAGE_B (4 * TILE_B)
#define GEMM_SMEM (2 * STAGE_B)

__device__ __forceinline__ void cpa_tile(uint32_t sbase,
                                         const __nv_bfloat16* __restrict__ g,
                                         int row0, int k0, int K, int tid)
{
    #pragma unroll
    for (int i = 0; i < 2; i++) {
        int ch = tid + i * 256;
        int r  = ch >> 2;
        int cc = (ch & 3) * 8;
        uint32_t sa = sbase + r * ROWB + cc * 2;
        const void* ga = g + (size_t)(row0 + r) * K + k0 + cc;
        CP_ASYNC16(sa, ga);
    }
}

__global__ __launch_bounds__(256) void gemm_split(
    const __nv_bfloat16* __restrict__ Ah, const __nv_bfloat16* __restrict__ Al,
    const __nv_bfloat16* __restrict__ Bh, const __nv_bfloat16* __restrict__ Bl,
    float* __restrict__ C, int M, int N, int K)
{
    extern __shared__ char smem[];
    uint32_t sb = smem_u32(smem);
    const int tid  = threadIdx.x;
    const int lane = tid & 31;
    const int wid  = tid >> 5;
    const int wm   = wid >> 2;
    const int wn   = wid & 3;
    const int m0 = blockIdx.y * BM;
    const int n0 = blockIdx.x * BN;
    const int NC = K / BKC;

    float acc[4][4][4] = {};

    cpa_tile(sb,              Ah, m0, 0, K, tid);
    cpa_tile(sb + TILE_B,     Al, m0, 0, K, tid);
    cpa_tile(sb + 2 * TILE_B, Bh, n0, 0, K, tid);
    cpa_tile(sb + 3 * TILE_B, Bl, n0, 0, K, tid);
    CP_COMMIT();
    CP_WAIT0();
    __syncthreads();

    const int lm  = lane & 15;
    const int lk8 = (lane >> 4) * 8;

    for (int c = 0; c < NC; c++) {
        uint32_t sbuf = sb + (c & 1) * STAGE_B;
        if (c + 1 < NC) {
            uint32_t snext = sb + ((c + 1) & 1) * STAGE_B;
            int k0 = (c + 1) * BKC;
            cpa_tile(snext,              Ah, m0, k0, K, tid);
            cpa_tile(snext + TILE_B,     Al, m0, k0, K, tid);
            cpa_tile(snext + 2 * TILE_B, Bh, n0, k0, K, tid);
            cpa_tile(snext + 3 * TILE_B, Bl, n0, k0, K, tid);
            CP_COMMIT();
        }

        uint32_t sA  = sbuf;
        uint32_t sAl = sbuf + TILE_B;
        uint32_t sB  = sbuf + 2 * TILE_B;
        uint32_t sBl = sbuf + 3 * TILE_B;

        #pragma unroll
        for (int ks = 0; ks < 2; ks++) {
            uint32_t kb = (ks * 16 + lk8) * 2;
            uint32_t ah[4][4], al[4][4], bh[2][4], bl[2][4];
            #pragma unroll
            for (int mf = 0; mf < 4; mf++) {
                uint32_t ro = (wm * 64 + mf * 16 + lm) * ROWB + kb;
                ldsm4(ah[mf], sA + ro);
                ldsm4(al[mf], sAl + ro);
            }
            #pragma unroll
            for (int nf2 = 0; nf2 < 2; nf2++) {
                uint32_t ro = (wn * 32 + nf2 * 16 + lm) * ROWB + kb;
                ldsm4(bh[nf2], sB + ro);
                ldsm4(bl[nf2], sBl + ro);
            }
            #pragma unroll
            for (int mf = 0; mf < 4; mf++)
                #pragma unroll
                for (int nf = 0; nf < 4; nf++) {
                    uint32_t b0h = bh[nf >> 1][nf & 1];
                    uint32_t b1h = bh[nf >> 1][(nf & 1) + 2];
                    uint32_t b0l = bl[nf >> 1][nf & 1];
                    uint32_t b1l = bl[nf >> 1][(nf & 1) + 2];
                    mma16816(acc[mf][nf], ah[mf], b0h, b1h);
                    mma16816(acc[mf][nf], ah[mf], b0l, b1l);
                    mma16816(acc[mf][nf], al[mf], b0h, b1h);
                }
        }

        if (c + 1 < NC) {
            CP_WAIT0();
            __syncthreads();
        }
    }

    int mbase = m0 + wm * 64;
    int nbase = n0 + wn * 32;
    #pragma unroll
    for (int mf = 0; mf < 4; mf++)
        #pragma unroll
        for (int nf = 0; nf < 4; nf++) {
            int r0 = mbase + mf * 16 + (lane >> 2);
            int c0 = nbase + nf * 8 + (lane & 3) * 2;
            *(float2*)&C[(size_t)r0 * N + c0] =
                make_float2(acc[mf][nf][0], acc[mf][nf][1]);
            *(float2*)&C[(size_t)(r0 + 8) * N + c0] =
                make_float2(acc[mf][nf][2], acc[mf][nf][3]);
        }
}

// =================================================================
// L2-normalize q,k and emit bf16 directly to g_qbh / g_kbh.
// One warp per (t, h, q-or-k) 128-float segment.
// =================================================================
__global__ __launch_bounds__(256) void l2norm_qk()
{
    int gw = blockIdx.x * 8 + (threadIdx.x >> 5);
    int l  = threadIdx.x & 31;
    int which = gw >> 16;           // 0 = q, 1 = k
    int rem   = gw & 65535;
    int t = rem >> 4;
    int h = rem & 15;

    const float* p = g_qkv + (size_t)t * TD3 + which * D_ + h * HD_ + l * 4;
    float4 v = *(const float4*)p;
    float ss = v.x * v.x + v.y * v.y + v.z * v.z + v.w * v.w;
    #pragma unroll
    for (int o = 16; o; o >>= 1) ss += __shfl_xor_sync(0xffffffffu, ss, o);
    float inv = 1.0f / fmaxf(sqrtf(ss), 1e-12f);
    __nv_bfloat162 h0 = __floats2bfloat162_rn(v.x * inv, v.y * inv);
    __nv_bfloat162 h1 = __floats2bfloat162_rn(v.z * inv, v.w * inv);
    uint2 hv;
    hv.x = *reinterpret_cast<unsigned*>(&h0);
    hv.y = *reinterpret_cast<unsigned*>(&h1);
    __nv_bfloat16* dst = which ? g_kbh : g_qbh;
    *(uint2*)(dst + (size_t)t * D_ + h * HD_ + l * 4) = hv;
}

// =================================================================
// Tensor-core flash attention.
// grid (T/128, H), 256 thr (8 warps). Warp w owns q-rows 16w..16w+15.
// Key tile = 64. S = Q K^T bf16; P*V split (Ph*Vh + Ph*Vl + Pl*Vh).
// smem: Q[128][136]b16, K[64][136]b16, Vt_hi[128][72]b16, Vt_lo[128][72]b16
// =================================================================
#define AQ_ROWB 272
#define AK_ROWB 272
#define AV_ROWB 144
#define AQ_OFF  0
#define AK_OFF  (128 * AQ_ROWB)            // 34816
#define AVH_OFF (AK_OFF + 64 * AK_ROWB)    // 52224
#define AVL_OFF (AVH_OFF + 128 * AV_ROWB)  // 70656
#define ATTN2_SMEM (AVL_OFF + 128 * AV_ROWB)   // 89088

__global__ __launch_bounds__(256, 2) void attn2(const float* __restrict__ mask)
{
    extern __shared__ char sm2[];
    uint32_t sb = smem_u32(sm2);
    const int tid = threadIdx.x, lane = tid & 31, w = tid >> 5;
    const int g = lane >> 2, q4 = lane & 3;
    const int lm = lane & 15, lk8 = (lane >> 4) * 8;
    const int q0 = blockIdx.x * 128, h = blockIdx.y;
    const float scale = 0.08838834764831845f;   // 128^-0.5

    // ---- load Q tile once: 128 rows x 256 B ----
    #pragma unroll
    for (int i = 0; i < 8; i++) {
        int ch = tid + i * 256;
        int r = ch >> 4, cc = ch & 15;
        CP_ASYNC16(sb + AQ_OFF + r * AQ_ROWB + cc * 16,
                   g_qbh + (size_t)(q0 + r) * D_ + h * HD_ + cc * 8);
    }
    CP_COMMIT();

    float o[16][4] = {};
    float m0 = -INFINITY, m1 = -INFINITY, l0 = 0.f, l1 = 0.f;
    const int row0 = q0 + w * 16 + g;

    for (int kt = 0; kt < T_; kt += 64) {
        __syncthreads();   // previous tile's compute done before overwrite
        // ---- K tile: 64 rows x 256 B ----
        #pragma unroll
        for (int i = 0; i < 4; i++) {
            int ch = tid + i * 256;
            int r = ch >> 4, cc = ch & 15;
            CP_ASYNC16(sb + AK_OFF + r * AK_ROWB + cc * 16,
                       g_kbh + (size_t)(kt + r) * D_ + h * HD_ + cc * 8);
        }
        // ---- Vt hi/lo tiles: 128 rows x 128 B each ----
        #pragma unroll
        for (int i = 0; i < 4; i++) {
            int ch = tid + i * 256;
            int r = ch >> 3, cc = ch & 7;
            CP_ASYNC16(sb + AVH_OFF + r * AV_ROWB + cc * 16,
                       g_vth + (size_t)h * HD_ * T_ + (size_t)r * T_ + kt + cc * 8);
        }
        #pragma unroll
        for (int i = 0; i < 4; i++) {
            int ch = tid + i * 256;
            int r = ch >> 3, cc = ch & 7;
            CP_ASYNC16(sb + AVL_OFF + r * AV_ROWB + cc * 16,
                       g_vtl + (size_t)h * HD_ * T_ + (size_t)r * T_ + kt + cc * 8);
        }
        CP_COMMIT();
        CP_WAIT0();
        __syncthreads();

        // ---- S = Q K^T : warp rows 16w..16w+15, cols 0..63 ----
        float s[8][4] = {};
        #pragma unroll
        for (int ks = 0; ks < 8; ks++) {
            uint32_t kbyte = (ks * 16 + lk8) * 2;
            uint32_t aq[4], kf[4][4];
            ldsm4(aq, sb + AQ_OFF + (w * 16 + lm) * AQ_ROWB + kbyte);
            #pragma unroll
            for (int n2 = 0; n2 < 4; n2++)
                ldsm4(kf[n2], sb + AK_OFF + (n2 * 16 + lm) * AK_ROWB + kbyte);
            #pragma unroll
            for (int nf = 0; nf < 8; nf++)
                mma16816(s[nf], aq, kf[nf >> 1][nf & 1], kf[nf >> 1][(nf & 1) + 2]);
        }

        // ---- scale + mask ----
        const float* mp0 = mask + (size_t)row0 * T_ + kt + q4 * 2;
        const float* mp1 = mp0 + 8 * T_;
        #pragma unroll
        for (int nf = 0; nf < 8; nf++) {
            float2 f0 = *(const float2*)(mp0 + nf * 8);
            float2 f1 = *(const float2*)(mp1 + nf * 8);
            s[nf][0] = s[nf][0] * scale + f0.x;
            s[nf][1] = s[nf][1] * scale + f0.y;
            s[nf][2] = s[nf][2] * scale + f1.x;
            s[nf][3] = s[nf][3] * scale + f1.y;
        }

        // ---- online softmax (rows row0, row0+8) ----
        float mx0 = s[0][0], mx1 = s[0][2];
        #pragma unroll
        for (int nf = 0; nf < 8; nf++) {
            mx0 = fmaxf(mx0, fmaxf(s[nf][0], s[nf][1]));
            mx1 = fmaxf(mx1, fmaxf(s[nf][2], s[nf][3]));
        }
        mx0 = fmaxf(mx0, __shfl_xor_sync(0xffffffffu, mx0, 1));
        mx0 = fmaxf(mx0, __shfl_xor_sync(0xffffffffu, mx0, 2));
        mx1 = fmaxf(mx1, __shfl_xor_sync(0xffffffffu, mx1, 1));
        mx1 = fmaxf(mx1, __shfl_xor_sync(0xffffffffu, mx1, 2));
        float mn0 = fmaxf(m0, mx0), mn1 = fmaxf(m1, mx1);
        float c0 = __expf(m0 - mn0), c1 = __expf(m1 - mn1);
        m0 = mn0; m1 = mn1;
        float sum0 = 0.f, sum1 = 0.f;
        #pragma unroll
        for (int nf = 0; nf < 8; nf++) {
            s[nf][0] = __expf(s[nf][0] - mn0);
            s[nf][1] = __expf(s[nf][1] - mn0);
            s[nf][2] = __expf(s[nf][2] - mn1);
            s[nf][3] = __expf(s[nf][3] - mn1);
            sum0 += s[nf][0] + s[nf][1];
            sum1 += s[nf][2] + s[nf][3];
        }
        sum0 += __shfl_xor_sync(0xffffffffu, sum0, 1);
        sum0 += __shfl_xor_sync(0xffffffffu, sum0, 2);
        sum1 += __shfl_xor_sync(0xffffffffu, sum1, 1);
        sum1 += __shfl_xor_sync(0xffffffffu, sum1, 2);
        l0 = l0 * c0 + sum0;
        l1 = l1 * c1 + sum1;
        #pragma unroll
        for (int nf = 0; nf < 16; nf++) {
            o[nf][0] *= c0; o[nf][1] *= c0;
            o[nf][2] *= c1; o[nf][3] *= c1;
        }

        // ---- O += P V (split: Ph*Vh + Ph*Vl + Pl*Vh) ----
        #pragma unroll
        for (int j = 0; j < 4; j++) {       // key 16-blocks
            // P fragments directly from S accumulators (C->A layout identity)
            uint32_t ph[4], pl[4];
            #pragma unroll
            for (int u = 0; u < 2; u++) {   // frags 2j, 2j+1 -> a0/a1, a2/a3
                float a = s[2 * j + u][0], b = s[2 * j + u][1];
                float cme = s[2 * j + u][2], d = s[2 * j + u][3];
                __nv_bfloat162 hab = __floats2bfloat162_rn(a, b);
                __nv_bfloat162 hcd = __floats2bfloat162_rn(cme, d);
                __nv_bfloat162 lab = __floats2bfloat162_rn(
                    a - __low2float(hab), b - __high2float(hab));
                __nv_bfloat162 lcd = __floats2bfloat162_rn(
                    cme - __low2float(hcd), d - __high2float(hcd));
                ph[2 * u]     = *reinterpret_cast<unsigned*>(&hab);
                ph[2 * u + 1] = *reinterpret_cast<unsigned*>(&hcd);
                pl[2 * u]     = *reinterpret_cast<unsigned*>(&lab);
                pl[2 * u + 1] = *reinterpret_cast<unsigned*>(&lcd);
            }
            uint32_t kb = (j * 16 + lk8) * 2;
            #pragma unroll
            for (int n2 = 0; n2 < 8; n2++) {    // d 16-blocks
                uint32_t vh[4], vl[4];
                uint32_t ro = (n2 * 16 + lm) * AV_ROWB + kb;
                ldsm4(vh, sb + AVH_OFF + ro);
                ldsm4(vl, sb + AVL_OFF + ro);
                mma16816(o[2 * n2],     ph, vh[0], vh[2]);
                mma16816(o[2 * n2 + 1], ph, vh[1], vh[3]);
                mma16816(o[2 * n2],     ph, vl[0], vl[2]);
                mma16816(o[2 * n2 + 1], ph, vl[1], vl[3]);
                mma16816(o[2 * n2],     pl, vh[0], vh[2]);
                mma16816(o[2 * n2 + 1], pl, vh[1], vh[3]);
            }
        }
    }

    // ---- epilogue ----
    float inv0 = 1.f / l0, inv1 = 1.f / l1;
    float* op0 = g_ao + (size_t)row0 * D_ + h * HD_ + q4 * 2;
    float* op1 = op0 + 8 * D_;
    #pragma unroll
    for (int nf = 0; nf < 16; nf++) {
        *(float2*)(op0 + nf * 8) = make_float2(o[nf][0] * inv0, o[nf][1] * inv0);
        *(float2*)(op1 + nf * 8) = make_float2(o[nf][2] * inv1, o[nf][3] * inv1);
    }
}

// =================================================================
// Launch
// =================================================================
extern "C" void kernel_launch(void* const* d_in, const int* in_sizes, int n_in,
                              void* d_out, int out_size)
{
    const float* x    = (const float*)d_in[0];
    const float* mask = (const float*)d_in[1];
    const float* Wqkv = (const float*)d_in[2];
    const float* Wout = (const float*)d_in[3];
    float* out = (float*)d_out;

    float *qkv, *ao;
    __nv_bfloat16 *xh, *xl, *wqh, *wql, *woh, *wol, *aoh, *aol;
    cudaGetSymbolAddress((void**)&qkv, g_qkv);
    cudaGetSymbolAddress((void**)&ao,  g_ao);
    cudaGetSymbolAddress((void**)&xh,  g_xh);
    cudaGetSymbolAddress((void**)&xl,  g_xl);
    cudaGetSymbolAddress((void**)&wqh, g_wqh);
    cudaGetSymbolAddress((void**)&wql, g_wql);
    cudaGetSymbolAddress((void**)&woh, g_woh);
    cudaGetSymbolAddress((void**)&wol, g_wol);
    cudaGetSymbolAddress((void**)&aoh, g_aoh);
    cudaGetSymbolAddress((void**)&aol, g_aol);

    cudaFuncSetAttribute(gemm_split,
                         cudaFuncAttributeMaxDynamicSharedMemorySize, GEMM_SMEM);
    cudaFuncSetAttribute(attn2,
                         cudaFuncAttributeMaxDynamicSharedMemorySize, ATTN2_SMEM);

    // 1) split x and weights (weights transposed to [N][K])
    split_hl<<<(T_ * D_ / 4) / 256, 256>>>((const float4*)x, (uint2*)xh, (uint2*)xl);
    tsplit<<<dim3(TD3 / 32, D_ / 32), dim3(32, 8)>>>(Wqkv, wqh, wql, D_, TD3);
    tsplit<<<dim3(D_ / 32,  D_ / 32), dim3(32, 8)>>>(Wout, woh, wol, D_, D_);

    // 2) qkv = x @ W_qkv
    gemm_split<<<dim3(TD3 / BN, T_ / BM), 256, GEMM_SMEM>>>(
        xh, xl, wqh, wql, qkv, T_, TD3, D_);

    // 3) normalize q,k -> bf16; transpose+split V per head
    l2norm_qk<<<(T_ * H_ * 2) / 8, 256>>>();
    vtsplit<<<dim3(T_ / 32, HD_ / 32, H_), dim3(32, 8)>>>();

    // 4) tensor-core flash attention -> g_ao
    attn2<<<dim3(T_ / 128, H_), 256, ATTN2_SMEM>>>(mask);

    // 5) out = ao @ W_out
    split_hl<<<(T_ * D_ / 4) / 256, 256>>>((const float4*)ao, (uint2*)aoh, (uint2*)aol);
    gemm_split<<<dim3(D_ / BN, T_ / BM), 256, GEMM_SMEM>>>(
        aoh, aol, woh, wol, out, T_, D_, D_);
}

// round 6
// speedup vs baseline: 3.1400x; 1.0105x over previous
#include <cuda_runtime.h>
#include <cuda_bf16.h>
#include <math.h>
#include <stdint.h>

#define T_   4096
#define D_   2048
#define H_   16
#define HD_  128
#define TD3  6144   // 3*D

// ---------------- scratch (no allocations allowed) ----------------
__device__ float g_qkv[(size_t)T_ * TD3];   // [q | k | v] per row, fp32

// split-precision bf16 buffers for dense GEMMs
__device__ __nv_bfloat16 g_xh[(size_t)T_ * D_];
__device__ __nv_bfloat16 g_xl[(size_t)T_ * D_];
__device__ __nv_bfloat16 g_wqh[(size_t)TD3 * D_];   // Wqkv^T  [6144][2048]
__device__ __nv_bfloat16 g_wql[(size_t)TD3 * D_];
__device__ __nv_bfloat16 g_woh[(size_t)D_ * D_];    // Wout^T  [2048][2048]
__device__ __nv_bfloat16 g_wol[(size_t)D_ * D_];
__device__ __nv_bfloat16 g_aoh[(size_t)T_ * D_];
__device__ __nv_bfloat16 g_aol[(size_t)T_ * D_];

// attention bf16 operands
__device__ __nv_bfloat16 g_qbh[(size_t)T_ * D_];          // normalized q*scale, bf16
__device__ __nv_bfloat16 g_kbh[(size_t)T_ * D_];          // normalized k, bf16
__device__ __nv_bfloat16 g_vth[(size_t)H_ * HD_ * T_];    // V^T per head, hi
__device__ __nv_bfloat16 g_vtl[(size_t)H_ * HD_ * T_];    // V^T per head, lo
__device__ __nv_bfloat16 g_maskb[(size_t)T_ * T_];        // mask in bf16

// =================================================================
// PTX helpers (portable: ldmatrix / mma.sync / cp.async)
// =================================================================
__device__ __forceinline__ uint32_t smem_u32(const void* p) {
    uint32_t a;
    asm("{ .reg .u64 t; cvta.to.shared.u64 t, %1; cvt.u32.u64 %0, t; }"
        : "=r"(a) : "l"(p));
    return a;
}
__device__ __forceinline__ void ldsm4(uint32_t* r, uint32_t a) {
    asm volatile("ldmatrix.sync.aligned.m8n8.x4.shared.b16 {%0,%1,%2,%3}, [%4];"
                 : "=r"(r[0]), "=r"(r[1]), "=r"(r[2]), "=r"(r[3]) : "r"(a));
}
__device__ __forceinline__ void mma16816(float* c, const uint32_t* a,
                                         uint32_t b0, uint32_t b1) {
    asm volatile(
        "mma.sync.aligned.m16n8k16.row.col.f32.bf16.bf16.f32 "
        "{%0,%1,%2,%3}, {%4,%5,%6,%7}, {%8,%9}, {%0,%1,%2,%3};"
        : "+f"(c[0]), "+f"(c[1]), "+f"(c[2]), "+f"(c[3])
        : "r"(a[0]), "r"(a[1]), "r"(a[2]), "r"(a[3]), "r"(b0), "r"(b1));
}
#define CP_ASYNC16(sa, ga) \
    asm volatile("cp.async.cg.shared.global [%0], [%1], 16;" :: "r"(sa), "l"(ga))
#define CP_COMMIT() asm volatile("cp.async.commit_group;" ::: "memory")
#define CP_WAIT0()  asm volatile("cp.async.wait_group 0;" ::: "memory")

// =================================================================
// Split / transpose / convert kernels
// =================================================================
__global__ __launch_bounds__(256) void split_hl(const float4* __restrict__ src,
                                                uint2* __restrict__ hi,
                                                uint2* __restrict__ lo)
{
    size_t i = (size_t)blockIdx.x * 256 + threadIdx.x;
    float4 v = src[i];
    __nv_bfloat162 h0 = __floats2bfloat162_rn(v.x, v.y);
    __nv_bfloat162 h1 = __floats2bfloat162_rn(v.z, v.w);
    float rx = v.x - __low2float(h0),  ry = v.y - __high2float(h0);
    float rz = v.z - __low2float(h1),  rw = v.w - __high2float(h1);
    __nv_bfloat162 l0 = __floats2bfloat162_rn(rx, ry);
    __nv_bfloat162 l1 = __floats2bfloat162_rn(rz, rw);
    uint2 hv, lv;
    hv.x = *reinterpret_cast<unsigned*>(&h0); hv.y = *reinterpret_cast<unsigned*>(&h1);
    lv.x = *reinterpret_cast<unsigned*>(&l0); lv.y = *reinterpret_cast<unsigned*>(&l1);
    hi[i] = hv;
    lo[i] = lv;
}

__global__ __launch_bounds__(256) void mask2bf(const float4* __restrict__ m)
{
    size_t i = (size_t)blockIdx.x * 256 + threadIdx.x;
    float4 v = m[i];
    __nv_bfloat162 a = __floats2bfloat162_rn(v.x, v.y);
    __nv_bfloat162 b = __floats2bfloat162_rn(v.z, v.w);
    uint2 o;
    o.x = *reinterpret_cast<unsigned*>(&a);
    o.y = *reinterpret_cast<unsigned*>(&b);
    ((uint2*)g_maskb)[i] = o;
}

// src[R][C] fp32  ->  out[C][R] bf16 hi/lo (transpose + split)
__global__ __launch_bounds__(256) void tsplit(const float* __restrict__ src,
                                              __nv_bfloat16* __restrict__ dh,
                                              __nv_bfloat16* __restrict__ dl,
                                              int R, int C)
{
    __shared__ float tile[32][33];
    int tx = threadIdx.x, ty = threadIdx.y;
    int x0 = blockIdx.x * 32, y0 = blockIdx.y * 32;
    #pragma unroll
    for (int j = 0; j < 4; j++)
        tile[ty + j * 8][tx] = src[(size_t)(y0 + ty + j * 8) * C + x0 + tx];
    __syncthreads();
    #pragma unroll
    for (int j = 0; j < 4; j++) {
        float v = tile[tx][ty + j * 8];
        __nv_bfloat16 h = __float2bfloat16(v);
        __nv_bfloat16 l = __float2bfloat16(v - __bfloat162float(h));
        size_t o = (size_t)(x0 + ty + j * 8) * R + y0 + tx;
        dh[o] = h;
        dl[o] = l;
    }
}

// V region of g_qkv -> per-head transposed split: g_vt{h,l}[h][d][t]
__global__ __launch_bounds__(256) void vtsplit()
{
    __shared__ float tile[32][33];
    int tx = threadIdx.x, ty = threadIdx.y;
    int t0 = blockIdx.x * 32, d0 = blockIdx.y * 32, h = blockIdx.z;
    #pragma unroll
    for (int j = 0; j < 4; j++)
        tile[ty + j * 8][tx] =
            g_qkv[(size_t)(t0 + ty + j * 8) * TD3 + 2 * D_ + h * HD_ + d0 + tx];
    __syncthreads();
    size_t base = (size_t)h * HD_ * T_;
    #pragma unroll
    for (int j = 0; j < 4; j++) {
        float v = tile[tx][ty + j * 8];
        __nv_bfloat16 hh = __float2bfloat16(v);
        __nv_bfloat16 ll = __float2bfloat16(v - __bfloat162float(hh));
        size_t o = base + (size_t)(d0 + ty + j * 8) * T_ + t0 + tx;
        g_vth[o] = hh;
        g_vtl[o] = ll;
    }
}

// =================================================================
// Split-bf16 mma.sync GEMM (unchanged — passing, tensor=52.8%)
// =================================================================
#define BM 128
#define BN 128
#define BKC 32
#define ROWB 80
#define TILE_B (128 * ROWB)
#define STAGE_B (4 * TILE_B)
#define GEMM_SMEM (2 * STAGE_B)

__device__ __forceinline__ void cpa_tile(uint32_t sbase,
                                         const __nv_bfloat16* __restrict__ g,
                                         int row0, int k0, int K, int tid)
{
    #pragma unroll
    for (int i = 0; i < 2; i++) {
        int ch = tid + i * 256;
        int r  = ch >> 2;
        int cc = (ch & 3) * 8;
        uint32_t sa = sbase + r * ROWB + cc * 2;
        const void* ga = g + (size_t)(row0 + r) * K + k0 + cc;
        CP_ASYNC16(sa, ga);
    }
}

__global__ __launch_bounds__(256) void gemm_split(
    const __nv_bfloat16* __restrict__ Ah, const __nv_bfloat16* __restrict__ Al,
    const __nv_bfloat16* __restrict__ Bh, const __nv_bfloat16* __restrict__ Bl,
    float* __restrict__ C, int M, int N, int K)
{
    extern __shared__ char smem[];
    uint32_t sb = smem_u32(smem);
    const int tid  = threadIdx.x;
    const int lane = tid & 31;
    const int wid  = tid >> 5;
    const int wm   = wid >> 2;
    const int wn   = wid & 3;
    const int m0 = blockIdx.y * BM;
    const int n0 = blockIdx.x * BN;
    const int NC = K / BKC;

    float acc[4][4][4] = {};

    cpa_tile(sb,              Ah, m0, 0, K, tid);
    cpa_tile(sb + TILE_B,     Al, m0, 0, K, tid);
    cpa_tile(sb + 2 * TILE_B, Bh, n0, 0, K, tid);
    cpa_tile(sb + 3 * TILE_B, Bl, n0, 0, K, tid);
    CP_COMMIT();
    CP_WAIT0();
    __syncthreads();

    const int lm  = lane & 15;
    const int lk8 = (lane >> 4) * 8;

    for (int c = 0; c < NC; c++) {
        uint32_t sbuf = sb + (c & 1) * STAGE_B;
        if (c + 1 < NC) {
            uint32_t snext = sb + ((c + 1) & 1) * STAGE_B;
            int k0 = (c + 1) * BKC;
            cpa_tile(snext,              Ah, m0, k0, K, tid);
            cpa_tile(snext + TILE_B,     Al, m0, k0, K, tid);
            cpa_tile(snext + 2 * TILE_B, Bh, n0, k0, K, tid);
            cpa_tile(snext + 3 * TILE_B, Bl, n0, k0, K, tid);
            CP_COMMIT();
        }

        uint32_t sA  = sbuf;
        uint32_t sAl = sbuf + TILE_B;
        uint32_t sB  = sbuf + 2 * TILE_B;
        uint32_t sBl = sbuf + 3 * TILE_B;

        #pragma unroll
        for (int ks = 0; ks < 2; ks++) {
            uint32_t kb = (ks * 16 + lk8) * 2;
            uint32_t ah[4][4], al[4][4], bh[2][4], bl[2][4];
            #pragma unroll
            for (int mf = 0; mf < 4; mf++) {
                uint32_t ro = (wm * 64 + mf * 16 + lm) * ROWB + kb;
                ldsm4(ah[mf], sA + ro);
                ldsm4(al[mf], sAl + ro);
            }
            #pragma unroll
            for (int nf2 = 0; nf2 < 2; nf2++) {
                uint32_t ro = (wn * 32 + nf2 * 16 + lm) * ROWB + kb;
                ldsm4(bh[nf2], sB + ro);
                ldsm4(bl[nf2], sBl + ro);
            }
            #pragma unroll
            for (int mf = 0; mf < 4; mf++)
                #pragma unroll
                for (int nf = 0; nf < 4; nf++) {
                    uint32_t b0h = bh[nf >> 1][nf & 1];
                    uint32_t b1h = bh[nf >> 1][(nf & 1) + 2];
                    uint32_t b0l = bl[nf >> 1][nf & 1];
                    uint32_t b1l = bl[nf >> 1][(nf & 1) + 2];
                    mma16816(acc[mf][nf], ah[mf], b0h, b1h);
                    mma16816(acc[mf][nf], ah[mf], b0l, b1l);
                    mma16816(acc[mf][nf], al[mf], b0h, b1h);
                }
        }

        if (c + 1 < NC) {
            CP_WAIT0();
            __syncthreads();
        }
    }

    int mbase = m0 + wm * 64;
    int nbase = n0 + wn * 32;
    #pragma unroll
    for (int mf = 0; mf < 4; mf++)
        #pragma unroll
        for (int nf = 0; nf < 4; nf++) {
            int r0 = mbase + mf * 16 + (lane >> 2);
            int c0 = nbase + nf * 8 + (lane & 3) * 2;
            *(float2*)&C[(size_t)r0 * N + c0] =
                make_float2(acc[mf][nf][0], acc[mf][nf][1]);
            *(float2*)&C[(size_t)(r0 + 8) * N + c0] =
                make_float2(acc[mf][nf][2], acc[mf][nf][3]);
        }
}

// =================================================================
// L2-normalize q,k -> bf16 (softmax scale folded into q).
// =================================================================
__global__ __launch_bounds__(256) void l2norm_qk()
{
    int gw = blockIdx.x * 8 + (threadIdx.x >> 5);
    int l  = threadIdx.x & 31;
    int which = gw >> 16;           // 0 = q, 1 = k
    int rem   = gw & 65535;
    int t = rem >> 4;
    int h = rem & 15;

    const float* p = g_qkv + (size_t)t * TD3 + which * D_ + h * HD_ + l * 4;
    float4 v = *(const float4*)p;
    float ss = v.x * v.x + v.y * v.y + v.z * v.z + v.w * v.w;
    #pragma unroll
    for (int o = 16; o; o >>= 1) ss += __shfl_xor_sync(0xffffffffu, ss, o);
    float sc = which ? 1.0f : 0.08838834764831845f;    // 128^-0.5 folded into q
    float inv = sc / fmaxf(sqrtf(ss), 1e-12f);
    __nv_bfloat162 h0 = __floats2bfloat162_rn(v.x * inv, v.y * inv);
    __nv_bfloat162 h1 = __floats2bfloat162_rn(v.z * inv, v.w * inv);
    uint2 hv;
    hv.x = *reinterpret_cast<unsigned*>(&h0);
    hv.y = *reinterpret_cast<unsigned*>(&h1);
    __nv_bfloat16* dst = which ? g_kbh : g_qbh;
    *(uint2*)(dst + (size_t)t * D_ + h * HD_ + l * 4) = hv;
}

// =================================================================
// Tensor-core flash attention, pipelined.
// grid (H, T/128), 256 thr (8 warps), warp w owns q-rows 16w..16w+15.
// XOR-swizzled smem (no padding):
//   Q  128 x 256B  (32 KB)
//   K   64 x 256B  (16 KB, single buffer, reloaded after S)
//   V  2 stages x (Vh 128x128B + Vl 128x128B) (2 x 32 KB)
// Total 112 KB -> 2 CTAs/SM.
// =================================================================
#define AQ_OFF2 0
#define AK_OFF2 32768
#define AVH2(s) (49152 + (s) * 32768)
#define AVL2(s) (49152 + (s) * 32768 + 16384)
#define ATTN2_SMEM 114688
#define NT_ (T_ / 64)

__global__ __launch_bounds__(256, 2) void attn2()
{
    extern __shared__ char sm2[];
    uint32_t sb = smem_u32(sm2);
    const int tid = threadIdx.x, lane = tid & 31, w = tid >> 5;
    const int g = lane >> 2, q4 = lane & 3;
    const int lm = lane & 15, lhi = lane >> 4;
    const int h = blockIdx.x, q0 = blockIdx.y * 128;

    const size_t vbase = (size_t)h * HD_ * T_;

    // ---- prologue: Q + K(0) + V(0) ----
    #pragma unroll
    for (int i = 0; i < 8; i++) {
        int ch = tid + i * 256;
        int r = ch >> 4, c = ch & 15;
        CP_ASYNC16(sb + AQ_OFF2 + r * 256 + ((c ^ (r & 7)) << 4),
                   g_qbh + (size_t)(q0 + r) * D_ + h * HD_ + c * 8);
    }
    #pragma unroll
    for (int i = 0; i < 4; i++) {
        int ch = tid + i * 256;
        int r = ch >> 4, c = ch & 15;
        CP_ASYNC16(sb + AK_OFF2 + r * 256 + ((c ^ (r & 7)) << 4),
                   g_kbh + (size_t)r * D_ + h * HD_ + c * 8);
    }
    #pragma unroll
    for (int i = 0; i < 4; i++) {
        int ch = tid + i * 256;
        int r = ch >> 3, c = ch & 7;
        uint32_t so = r * 128 + ((c ^ (r & 7)) << 4);
        CP_ASYNC16(sb + AVH2(0) + so, g_vth + vbase + (size_t)r * T_ + c * 8);
        CP_ASYNC16(sb + AVL2(0) + so, g_vtl + vbase + (size_t)r * T_ + c * 8);
    }
    CP_COMMIT();

    float o[16][4] = {};
    float m0 = -INFINITY, m1 = -INFINITY, l0 = 0.f, l1 = 0.f;
    const int row0 = q0 + w * 16 + g;

    CP_WAIT0();
    __syncthreads();

    for (int ti = 0; ti < NT_; ti++) {
        const int kt = ti * 64;

        // ---- mask prefetch (bf16x2 regs) — issued before MMA block ----
        uint32_t mfr[16];
        {
            const __nv_bfloat16* mb0 = g_maskb + (size_t)row0 * T_ + kt + q4 * 2;
            #pragma unroll
            for (int nf = 0; nf < 8; nf++) {
                mfr[nf]     = *(const uint32_t*)(mb0 + nf * 8);
                mfr[8 + nf] = *(const uint32_t*)(mb0 + 8 * T_ + nf * 8);
            }
        }

        // ---- S = Q K^T (scale pre-folded into q) ----
        float s[8][4] = {};
        #pragma unroll
        for (int ks = 0; ks < 8; ks++) {
            int cb = ks * 2 + lhi;
            uint32_t aq[4];
            {
                int r = w * 16 + lm;
                ldsm4(aq, sb + AQ_OFF2 + r * 256 + ((cb ^ (r & 7)) << 4));
            }
            #pragma unroll
            for (int n2 = 0; n2 < 4; n2++) {
                uint32_t kf[4];
                int r = n2 * 16 + lm;
                ldsm4(kf, sb + AK_OFF2 + r * 256 + ((cb ^ (r & 7)) << 4));
                mma16816(s[2 * n2],     aq, kf[0], kf[2]);
                mma16816(s[2 * n2 + 1], aq, kf[1], kf[3]);
            }
        }

        __syncthreads();   // all warps done reading K(ti); V(ti-1) stage free

        // ---- issue K(ti+1), V(ti+1): overlap softmax + PV ----
        if (ti + 1 < NT_) {
            const int kn = kt + 64;
            const int sn = (ti + 1) & 1;
            #pragma unroll
            for (int i = 0; i < 4; i++) {
                int ch = tid + i * 256;
                int r = ch >> 4, c = ch & 15;
                CP_ASYNC16(sb + AK_OFF2 + r * 256 + ((c ^ (r & 7)) << 4),
                           g_kbh + (size_t)(kn + r) * D_ + h * HD_ + c * 8);
            }
            #pragma unroll
            for (int i = 0; i < 4; i++) {
                int ch = tid + i * 256;
                int r = ch >> 3, c = ch & 7;
                uint32_t so = r * 128 + ((c ^ (r & 7)) << 4);
                CP_ASYNC16(sb + AVH2(sn) + so,
                           g_vth + vbase + (size_t)r * T_ + kn + c * 8);
                CP_ASYNC16(sb + AVL2(sn) + so,
                           g_vtl + vbase + (size_t)r * T_ + kn + c * 8);
            }
            CP_COMMIT();
        }

        // ---- add mask ----
        #pragma unroll
        for (int nf = 0; nf < 8; nf++) {
            __nv_bfloat162 b0 = *reinterpret_cast<__nv_bfloat162*>(&mfr[nf]);
            __nv_bfloat162 b1 = *reinterpret_cast<__nv_bfloat162*>(&mfr[8 + nf]);
            s[nf][0] += __low2float(b0);
            s[nf][1] += __high2float(b0);
            s[nf][2] += __low2float(b1);
            s[nf][3] += __high2float(b1);
        }

        // ---- online softmax (rows row0, row0+8) ----
        float mx0 = s[0][0], mx1 = s[0][2];
        #pragma unroll
        for (int nf = 0; nf < 8; nf++) {
            mx0 = fmaxf(mx0, fmaxf(s[nf][0], s[nf][1]));
            mx1 = fmaxf(mx1, fmaxf(s[nf][2], s[nf][3]));
        }
        mx0 = fmaxf(mx0, __shfl_xor_sync(0xffffffffu, mx0, 1));
        mx0 = fmaxf(mx0, __shfl_xor_sync(0xffffffffu, mx0, 2));
        mx1 = fmaxf(mx1, __shfl_xor_sync(0xffffffffu, mx1, 1));
        mx1 = fmaxf(mx1, __shfl_xor_sync(0xffffffffu, mx1, 2));
        float mn0 = fmaxf(m0, mx0), mn1 = fmaxf(m1, mx1);
        float c0 = __expf(m0 - mn0), c1 = __expf(m1 - mn1);
        m0 = mn0; m1 = mn1;
        float sum0 = 0.f, sum1 = 0.f;
        #pragma unroll
        for (int nf = 0; nf < 8; nf++) {
            s[nf][0] = __expf(s[nf][0] - mn0);
            s[nf][1] = __expf(s[nf][1] - mn0);
            s[nf][2] = __expf(s[nf][2] - mn1);
            s[nf][3] = __expf(s[nf][3] - mn1);
            sum0 += s[nf][0] + s[nf][1];
            sum1 += s[nf][2] + s[nf][3];
        }
        sum0 += __shfl_xor_sync(0xffffffffu, sum0, 1);
        sum0 += __shfl_xor_sync(0xffffffffu, sum0, 2);
        sum1 += __shfl_xor_sync(0xffffffffu, sum1, 1);
        sum1 += __shfl_xor_sync(0xffffffffu, sum1, 2);
        l0 = l0 * c0 + sum0;
        l1 = l1 * c1 + sum1;
        #pragma unroll
        for (int nf = 0; nf < 16; nf++) {
            o[nf][0] *= c0; o[nf][1] *= c0;
            o[nf][2] *= c1; o[nf][3] *= c1;
        }

        // ---- O += P V (Ph*Vh + Ph*Vl + Pl*Vh) from V stage ti&1 ----
        const uint32_t vh_base = sb + AVH2(ti & 1);
        const uint32_t vl_base = sb + AVL2(ti & 1);
        #pragma unroll
        for (int j = 0; j < 4; j++) {
            uint32_t ph[4], pl[4];
            #pragma unroll
            for (int u = 0; u < 2; u++) {
                float a = s[2 * j + u][0], b = s[2 * j + u][1];
                float cc = s[2 * j + u][2], d = s[2 * j + u][3];
                __nv_bfloat162 hab = __floats2bfloat162_rn(a, b);
                __nv_bfloat162 hcd = __floats2bfloat162_rn(cc, d);
                __nv_bfloat162 lab = __floats2bfloat162_rn(
                    a - __low2float(hab), b - __high2float(hab));
                __nv_bfloat162 lcd = __floats2bfloat162_rn(
                    cc - __low2float(hcd), d - __high2float(hcd));
                ph[2 * u]     = *reinterpret_cast<unsigned*>(&hab);
                ph[2 * u + 1] = *reinterpret_cast<unsigned*>(&hcd);
                pl[2 * u]     = *reinterpret_cast<unsigned*>(&lab);
                pl[2 * u + 1] = *reinterpret_cast<unsigned*>(&lcd);
            }
            int cb = j * 2 + lhi;
            #pragma unroll
            for (int n2 = 0; n2 < 8; n2++) {
                uint32_t vh[4], vl[4];
                int r = n2 * 16 + lm;
                uint32_t so = r * 128 + ((cb ^ (r & 7)) << 4);
                ldsm4(vh, vh_base + so);
                ldsm4(vl, vl_base + so);
                mma16816(o[2 * n2],     ph, vh[0], vh[2]);
                mma16816(o[2 * n2 + 1], ph, vh[1], vh[3]);
                mma16816(o[2 * n2],     ph, vl[0], vl[2]);
                mma16816(o[2 * n2 + 1], ph, vl[1], vl[3]);
                mma16816(o[2 * n2],     pl, vh[0], vh[2]);
                mma16816(o[2 * n2 + 1], pl, vh[1], vh[3]);
            }
        }

        if (ti + 1 < NT_) {
            CP_WAIT0();
            __syncthreads();
        }
    }

    // ---- epilogue: normalize + bf16 hi/lo split directly ----
    float inv0 = 1.f / l0, inv1 = 1.f / l1;
    size_t base0 = (size_t)row0 * D_ + h * HD_ + q4 * 2;
    size_t base1 = base0 + (size_t)8 * D_;
    #pragma unroll
    for (int nf = 0; nf < 16; nf++) {
        float a = o[nf][0] * inv0, b = o[nf][1] * inv0;
        __nv_bfloat162 hb = __floats2bfloat162_rn(a, b);
        __nv_bfloat162 lb = __floats2bfloat162_rn(
            a - __low2float(hb), b - __high2float(hb));
        *(uint32_t*)(g_aoh + base0 + nf * 8) = *reinterpret_cast<unsigned*>(&hb);
        *(uint32_t*)(g_aol + base0 + nf * 8) = *reinterpret_cast<unsigned*>(&lb);
        float cme = o[nf][2] * inv1, d = o[nf][3] * inv1;
        __nv_bfloat162 hb1 = __floats2bfloat162_rn(cme, d);
        __nv_bfloat162 lb1 = __floats2bfloat162_rn(
            cme - __low2float(hb1), d - __high2float(hb1));
        *(uint32_t*)(g_aoh + base1 + nf * 8) = *reinterpret_cast<unsigned*>(&hb1);
        *(uint32_t*)(g_aol + base1 + nf * 8) = *reinterpret_cast<unsigned*>(&lb1);
    }
}

// =================================================================
// Launch
// =================================================================
extern "C" void kernel_launch(void* const* d_in, const int* in_sizes, int n_in,
                              void* d_out, int out_size)
{
    const float* x    = (const float*)d_in[0];
    const float* mask = (const float*)d_in[1];
    const float* Wqkv = (const float*)d_in[2];
    const float* Wout = (const float*)d_in[3];
    float* out = (float*)d_out;

    float* qkv;
    __nv_bfloat16 *xh, *xl, *wqh, *wql, *woh, *wol, *aoh, *aol;
    cudaGetSymbolAddress((void**)&qkv, g_qkv);
    cudaGetSymbolAddress((void**)&xh,  g_xh);
    cudaGetSymbolAddress((void**)&xl,  g_xl);
    cudaGetSymbolAddress((void**)&wqh, g_wqh);
    cudaGetSymbolAddress((void**)&wql, g_wql);
    cudaGetSymbolAddress((void**)&woh, g_woh);
    cudaGetSymbolAddress((void**)&wol, g_wol);
    cudaGetSymbolAddress((void**)&aoh, g_aoh);
    cudaGetSymbolAddress((void**)&aol, g_aol);

    cudaFuncSetAttribute(gemm_split,
                         cudaFuncAttributeMaxDynamicSharedMemorySize, GEMM_SMEM);
    cudaFuncSetAttribute(attn2,
                         cudaFuncAttributeMaxDynamicSharedMemorySize, ATTN2_SMEM);

    // 1) split x / weights; mask -> bf16
    split_hl<<<(T_ * D_ / 4) / 256, 256>>>((const float4*)x, (uint2*)xh, (uint2*)xl);
    tsplit<<<dim3(TD3 / 32, D_ / 32), dim3(32, 8)>>>(Wqkv, wqh, wql, D_, TD3);
    tsplit<<<dim3(D_ / 32,  D_ / 32), dim3(32, 8)>>>(Wout, woh, wol, D_, D_);
    mask2bf<<<(T_ * (size_t)T_ / 4) / 256, 256>>>((const float4*)mask);

    // 2) qkv = x @ W_qkv
    gemm_split<<<dim3(TD3 / BN, T_ / BM), 256, GEMM_SMEM>>>(
        xh, xl, wqh, wql, qkv, T_, TD3, D_);

    // 3) normalize q (scale folded), k -> bf16; transpose+split V
    l2norm_qk<<<(T_ * H_ * 2) / 8, 256>>>();
    vtsplit<<<dim3(T_ / 32, HD_ / 32, H_), dim3(32, 8)>>>();

    // 4) pipelined tensor-core flash attention -> g_aoh/g_aol
    attn2<<<dim3(H_, T_ / 128), 256, ATTN2_SMEM>>>();

    // 5) out = ao @ W_out
    gemm_split<<<dim3(D_ / BN, T_ / BM), 256, GEMM_SMEM>>>(
        aoh, aol, woh, wol, out, T_, D_, D_);
}

// round 7
// speedup vs baseline: 3.7216x; 1.1852x over previous
#include <cuda_runtime.h>
#include <cuda_bf16.h>
#include <cuda_fp16.h>
#include <math.h>
#include <stdint.h>

#define T_   4096
#define D_   2048
#define H_   16
#define HD_  128
#define TD3  6144   // 3*D

// ---------------- scratch (no allocations allowed) ----------------
__device__ float g_qkv[(size_t)T_ * TD3];   // [q | k | v] per row, fp32

// split-precision bf16 buffers for dense GEMMs
__device__ __nv_bfloat16 g_xh[(size_t)T_ * D_];
__device__ __nv_bfloat16 g_xl[(size_t)T_ * D_];
__device__ __nv_bfloat16 g_wqh[(size_t)TD3 * D_];   // Wqkv^T  [6144][2048]
__device__ __nv_bfloat16 g_wql[(size_t)TD3 * D_];
__device__ __nv_bfloat16 g_woh[(size_t)D_ * D_];    // Wout^T  [2048][2048]
__device__ __nv_bfloat16 g_wol[(size_t)D_ * D_];
__device__ __nv_bfloat16 g_aoh[(size_t)T_ * D_];
__device__ __nv_bfloat16 g_aol[(size_t)T_ * D_];

// attention fp16 operands
__device__ __half g_qfh[(size_t)T_ * D_];          // normalized q*scale, fp16
__device__ __half g_kfh[(size_t)T_ * D_];          // normalized k, fp16
__device__ __half g_vft[(size_t)H_ * HD_ * T_];    // V^T per head, fp16
__device__ __nv_bfloat16 g_maskb[(size_t)T_ * T_]; // mask in bf16

// =================================================================
// PTX helpers (portable: ldmatrix / mma.sync / cp.async)
// =================================================================
__device__ __forceinline__ uint32_t smem_u32(const void* p) {
    uint32_t a;
    asm("{ .reg .u64 t; cvta.to.shared.u64 t, %1; cvt.u32.u64 %0, t; }"
        : "=r"(a) : "l"(p));
    return a;
}
__device__ __forceinline__ void ldsm4(uint32_t* r, uint32_t a) {
    asm volatile("ldmatrix.sync.aligned.m8n8.x4.shared.b16 {%0,%1,%2,%3}, [%4];"
                 : "=r"(r[0]), "=r"(r[1]), "=r"(r[2]), "=r"(r[3]) : "r"(a));
}
__device__ __forceinline__ void mma16816(float* c, const uint32_t* a,
                                         uint32_t b0, uint32_t b1) {
    asm volatile(
        "mma.sync.aligned.m16n8k16.row.col.f32.bf16.bf16.f32 "
        "{%0,%1,%2,%3}, {%4,%5,%6,%7}, {%8,%9}, {%0,%1,%2,%3};"
        : "+f"(c[0]), "+f"(c[1]), "+f"(c[2]), "+f"(c[3])
        : "r"(a[0]), "r"(a[1]), "r"(a[2]), "r"(a[3]), "r"(b0), "r"(b1));
}
__device__ __forceinline__ void mma16816h(float* c, const uint32_t* a,
                                          uint32_t b0, uint32_t b1) {
    asm volatile(
        "mma.sync.aligned.m16n8k16.row.col.f32.f16.f16.f32 "
        "{%0,%1,%2,%3}, {%4,%5,%6,%7}, {%8,%9}, {%0,%1,%2,%3};"
        : "+f"(c[0]), "+f"(c[1]), "+f"(c[2]), "+f"(c[3])
        : "r"(a[0]), "r"(a[1]), "r"(a[2]), "r"(a[3]), "r"(b0), "r"(b1));
}
#define CP_ASYNC16(sa, ga) \
    asm volatile("cp.async.cg.shared.global [%0], [%1], 16;" :: "r"(sa), "l"(ga))
#define CP_COMMIT() asm volatile("cp.async.commit_group;" ::: "memory")
#define CP_WAIT0()  asm volatile("cp.async.wait_group 0;" ::: "memory")

// =================================================================
// Split / transpose / convert kernels
// =================================================================
__global__ __launch_bounds__(256) void split_hl(const float4* __restrict__ src,
                                                uint2* __restrict__ hi,
                                                uint2* __restrict__ lo)
{
    size_t i = (size_t)blockIdx.x * 256 + threadIdx.x;
    float4 v = src[i];
    __nv_bfloat162 h0 = __floats2bfloat162_rn(v.x, v.y);
    __nv_bfloat162 h1 = __floats2bfloat162_rn(v.z, v.w);
    float rx = v.x - __low2float(h0),  ry = v.y - __high2float(h0);
    float rz = v.z - __low2float(h1),  rw = v.w - __high2float(h1);
    __nv_bfloat162 l0 = __floats2bfloat162_rn(rx, ry);
    __nv_bfloat162 l1 = __floats2bfloat162_rn(rz, rw);
    uint2 hv, lv;
    hv.x = *reinterpret_cast<unsigned*>(&h0); hv.y = *reinterpret_cast<unsigned*>(&h1);
    lv.x = *reinterpret_cast<unsigned*>(&l0); lv.y = *reinterpret_cast<unsigned*>(&l1);
    hi[i] = hv;
    lo[i] = lv;
}

__global__ __launch_bounds__(256) void mask2bf(const float4* __restrict__ m)
{
    size_t i = (size_t)blockIdx.x * 256 + threadIdx.x;
    float4 v = m[i];
    __nv_bfloat162 a = __floats2bfloat162_rn(v.x, v.y);
    __nv_bfloat162 b = __floats2bfloat162_rn(v.z, v.w);
    uint2 o;
    o.x = *reinterpret_cast<unsigned*>(&a);
    o.y = *reinterpret_cast<unsigned*>(&b);
    ((uint2*)g_maskb)[i] = o;
}

// src[R][C] fp32  ->  out[C][R] bf16 hi/lo (transpose + split)
__global__ __launch_bounds__(256) void tsplit(const float* __restrict__ src,
                                              __nv_bfloat16* __restrict__ dh,
                                              __nv_bfloat16* __restrict__ dl,
                                              int R, int C)
{
    __shared__ float tile[32][33];
    int tx = threadIdx.x, ty = threadIdx.y;
    int x0 = blockIdx.x * 32, y0 = blockIdx.y * 32;
    #pragma unroll
    for (int j = 0; j < 4; j++)
        tile[ty + j * 8][tx] = src[(size_t)(y0 + ty + j * 8) * C + x0 + tx];
    __syncthreads();
    #pragma unroll
    for (int j = 0; j < 4; j++) {
        float v = tile[tx][ty + j * 8];
        __nv_bfloat16 h = __float2bfloat16(v);
        __nv_bfloat16 l = __float2bfloat16(v - __bfloat162float(h));
        size_t o = (size_t)(x0 + ty + j * 8) * R + y0 + tx;
        dh[o] = h;
        dl[o] = l;
    }
}

// V region of g_qkv -> per-head transposed fp16: g_vft[h][d][t]
__global__ __launch_bounds__(256) void vtsplit()
{
    __shared__ float tile[32][33];
    int tx = threadIdx.x, ty = threadIdx.y;
    int t0 = blockIdx.x * 32, d0 = blockIdx.y * 32, h = blockIdx.z;
    #pragma unroll
    for (int j = 0; j < 4; j++)
        tile[ty + j * 8][tx] =
            g_qkv[(size_t)(t0 + ty + j * 8) * TD3 + 2 * D_ + h * HD_ + d0 + tx];
    __syncthreads();
    size_t base = (size_t)h * HD_ * T_;
    #pragma unroll
    for (int j = 0; j < 4; j++) {
        float v = tile[tx][ty + j * 8];
        size_t o = base + (size_t)(d0 + ty + j * 8) * T_ + t0 + tx;
        g_vft[o] = __float2half(v);
    }
}

// =================================================================
// Split-bf16 mma.sync GEMM (unchanged — passing, tensor=52.8%)
// =================================================================
#define BM 128
#define BN 128
#define BKC 32
#define ROWB 80
#define TILE_B (128 * ROWB)
#define STAGE_B (4 * TILE_B)
#define GEMM_SMEM (2 * STAGE_B)

__device__ __forceinline__ void cpa_tile(uint32_t sbase,
                                         const __nv_bfloat16* __restrict__ g,
                                         int row0, int k0, int K, int tid)
{
    #pragma unroll
    for (int i = 0; i < 2; i++) {
        int ch = tid + i * 256;
        int r  = ch >> 2;
        int cc = (ch & 3) * 8;
        uint32_t sa = sbase + r * ROWB + cc * 2;
        const void* ga = g + (size_t)(row0 + r) * K + k0 + cc;
        CP_ASYNC16(sa, ga);
    }
}

__global__ __launch_bounds__(256) void gemm_split(
    const __nv_bfloat16* __restrict__ Ah, const __nv_bfloat16* __restrict__ Al,
    const __nv_bfloat16* __restrict__ Bh, const __nv_bfloat16* __restrict__ Bl,
    float* __restrict__ C, int M, int N, int K)
{
    extern __shared__ char smem[];
    uint32_t sb = smem_u32(smem);
    const int tid  = threadIdx.x;
    const int lane = tid & 31;
    const int wid  = tid >> 5;
    const int wm   = wid >> 2;
    const int wn   = wid & 3;
    const int m0 = blockIdx.y * BM;
    const int n0 = blockIdx.x * BN;
    const int NC = K / BKC;

    float acc[4][4][4] = {};

    cpa_tile(sb,              Ah, m0, 0, K, tid);
    cpa_tile(sb + TILE_B,     Al, m0, 0, K, tid);
    cpa_tile(sb + 2 * TILE_B, Bh, n0, 0, K, tid);
    cpa_tile(sb + 3 * TILE_B, Bl, n0, 0, K, tid);
    CP_COMMIT();
    CP_WAIT0();
    __syncthreads();

    const int lm  = lane & 15;
    const int lk8 = (lane >> 4) * 8;

    for (int c = 0; c < NC; c++) {
        uint32_t sbuf = sb + (c & 1) * STAGE_B;
        if (c + 1 < NC) {
            uint32_t snext = sb + ((c + 1) & 1) * STAGE_B;
            int k0 = (c + 1) * BKC;
            cpa_tile(snext,              Ah, m0, k0, K, tid);
            cpa_tile(snext + TILE_B,     Al, m0, k0, K, tid);
            cpa_tile(snext + 2 * TILE_B, Bh, n0, k0, K, tid);
            cpa_tile(snext + 3 * TILE_B, Bl, n0, k0, K, tid);
            CP_COMMIT();
        }

        uint32_t sA  = sbuf;
        uint32_t sAl = sbuf + TILE_B;
        uint32_t sB  = sbuf + 2 * TILE_B;
        uint32_t sBl = sbuf + 3 * TILE_B;

        #pragma unroll
        for (int ks = 0; ks < 2; ks++) {
            uint32_t kb = (ks * 16 + lk8) * 2;
            uint32_t ah[4][4], al[4][4], bh[2][4], bl[2][4];
            #pragma unroll
            for (int mf = 0; mf < 4; mf++) {
                uint32_t ro = (wm * 64 + mf * 16 + lm) * ROWB + kb;
                ldsm4(ah[mf], sA + ro);
                ldsm4(al[mf], sAl + ro);
            }
            #pragma unroll
            for (int nf2 = 0; nf2 < 2; nf2++) {
                uint32_t ro = (wn * 32 + nf2 * 16 + lm) * ROWB + kb;
                ldsm4(bh[nf2], sB + ro);
                ldsm4(bl[nf2], sBl + ro);
            }
            #pragma unroll
            for (int mf = 0; mf < 4; mf++)
                #pragma unroll
                for (int nf = 0; nf < 4; nf++) {
                    uint32_t b0h = bh[nf >> 1][nf & 1];
                    uint32_t b1h = bh[nf >> 1][(nf & 1) + 2];
                    uint32_t b0l = bl[nf >> 1][nf & 1];
                    uint32_t b1l = bl[nf >> 1][(nf & 1) + 2];
                    mma16816(acc[mf][nf], ah[mf], b0h, b1h);
                    mma16816(acc[mf][nf], ah[mf], b0l, b1l);
                    mma16816(acc[mf][nf], al[mf], b0h, b1h);
                }
        }

        if (c + 1 < NC) {
            CP_WAIT0();
            __syncthreads();
        }
    }

    int mbase = m0 + wm * 64;
    int nbase = n0 + wn * 32;
    #pragma unroll
    for (int mf = 0; mf < 4; mf++)
        #pragma unroll
        for (int nf = 0; nf < 4; nf++) {
            int r0 = mbase + mf * 16 + (lane >> 2);
            int c0 = nbase + nf * 8 + (lane & 3) * 2;
            *(float2*)&C[(size_t)r0 * N + c0] =
                make_float2(acc[mf][nf][0], acc[mf][nf][1]);
            *(float2*)&C[(size_t)(r0 + 8) * N + c0] =
                make_float2(acc[mf][nf][2], acc[mf][nf][3]);
        }
}

// =================================================================
// L2-normalize q,k -> fp16 (softmax scale folded into q).
// =================================================================
__global__ __launch_bounds__(256) void l2norm_qk()
{
    int gw = blockIdx.x * 8 + (threadIdx.x >> 5);
    int l  = threadIdx.x & 31;
    int which = gw >> 16;           // 0 = q, 1 = k
    int rem   = gw & 65535;
    int t = rem >> 4;
    int h = rem & 15;

    const float* p = g_qkv + (size_t)t * TD3 + which * D_ + h * HD_ + l * 4;
    float4 v = *(const float4*)p;
    float ss = v.x * v.x + v.y * v.y + v.z * v.z + v.w * v.w;
    #pragma unroll
    for (int o = 16; o; o >>= 1) ss += __shfl_xor_sync(0xffffffffu, ss, o);
    float sc = which ? 1.0f : 0.08838834764831845f;    // 128^-0.5 folded into q
    float inv = sc / fmaxf(sqrtf(ss), 1e-12f);
    __half2 h0 = __floats2half2_rn(v.x * inv, v.y * inv);
    __half2 h1 = __floats2half2_rn(v.z * inv, v.w * inv);
    uint2 hv;
    hv.x = *reinterpret_cast<unsigned*>(&h0);
    hv.y = *reinterpret_cast<unsigned*>(&h1);
    __half* dst = which ? g_kfh : g_qfh;
    *(uint2*)(dst + (size_t)t * D_ + h * HD_ + l * 4) = hv;
}

// =================================================================
// Tensor-core flash attention, fp16 operands, pipelined.
// grid (H, T/128), 256 thr (8 warps), warp w owns q-rows 16w..16w+15.
// XOR-swizzled smem:
//   Q  128 x 256B  (32 KB)
//   K   64 x 256B  (16 KB, single buffer, reloaded after S)
//   V  2 stages x 128x128B (2 x 16 KB)
// Total 80 KB -> 2 CTAs/SM.
// =================================================================
#define AQ_OFF2 0
#define AK_OFF2 32768
#define AV2(s)  (49152 + (s) * 16384)
#define ATTN2_SMEM 81920
#define NT_ (T_ / 64)

__global__ __launch_bounds__(256, 2) void attn2()
{
    extern __shared__ char sm2[];
    uint32_t sb = smem_u32(sm2);
    const int tid = threadIdx.x, lane = tid & 31, w = tid >> 5;
    const int g = lane >> 2, q4 = lane & 3;
    const int lm = lane & 15, lhi = lane >> 4;
    const int h = blockIdx.x, q0 = blockIdx.y * 128;

    const size_t vbase = (size_t)h * HD_ * T_;

    // ---- prologue: Q + K(0) + V(0) ----
    #pragma unroll
    for (int i = 0; i < 8; i++) {
        int ch = tid + i * 256;
        int r = ch >> 4, c = ch & 15;
        CP_ASYNC16(sb + AQ_OFF2 + r * 256 + ((c ^ (r & 7)) << 4),
                   g_qfh + (size_t)(q0 + r) * D_ + h * HD_ + c * 8);
    }
    #pragma unroll
    for (int i = 0; i < 4; i++) {
        int ch = tid + i * 256;
        int r = ch >> 4, c = ch & 15;
        CP_ASYNC16(sb + AK_OFF2 + r * 256 + ((c ^ (r & 7)) << 4),
                   g_kfh + (size_t)r * D_ + h * HD_ + c * 8);
    }
    #pragma unroll
    for (int i = 0; i < 4; i++) {
        int ch = tid + i * 256;
        int r = ch >> 3, c = ch & 7;
        uint32_t so = r * 128 + ((c ^ (r & 7)) << 4);
        CP_ASYNC16(sb + AV2(0) + so, g_vft + vbase + (size_t)r * T_ + c * 8);
    }
    CP_COMMIT();

    float o[16][4] = {};
    float m0 = -INFINITY, m1 = -INFINITY, l0 = 0.f, l1 = 0.f;
    const int row0 = q0 + w * 16 + g;

    CP_WAIT0();
    __syncthreads();

    for (int ti = 0; ti < NT_; ti++) {
        const int kt = ti * 64;

        // ---- mask prefetch (bf16x2 regs) — issued before MMA block ----
        uint32_t mfr[16];
        {
            const __nv_bfloat16* mb0 = g_maskb + (size_t)row0 * T_ + kt + q4 * 2;
            #pragma unroll
            for (int nf = 0; nf < 8; nf++) {
                mfr[nf]     = *(const uint32_t*)(mb0 + nf * 8);
                mfr[8 + nf] = *(const uint32_t*)(mb0 + 8 * T_ + nf * 8);
            }
        }

        // ---- S = Q K^T (scale pre-folded into q), fp16 ----
        float s[8][4] = {};
        #pragma unroll
        for (int ks = 0; ks < 8; ks++) {
            int cb = ks * 2 + lhi;
            uint32_t aq[4];
            {
                int r = w * 16 + lm;
                ldsm4(aq, sb + AQ_OFF2 + r * 256 + ((cb ^ (r & 7)) << 4));
            }
            #pragma unroll
            for (int n2 = 0; n2 < 4; n2++) {
                uint32_t kf[4];
                int r = n2 * 16 + lm;
                ldsm4(kf, sb + AK_OFF2 + r * 256 + ((cb ^ (r & 7)) << 4));
                mma16816h(s[2 * n2],     aq, kf[0], kf[2]);
                mma16816h(s[2 * n2 + 1], aq, kf[1], kf[3]);
            }
        }

        __syncthreads();   // all warps done reading K(ti)

        // ---- issue K(ti+1), V(ti+1): overlap softmax + PV ----
        if (ti + 1 < NT_) {
            const int kn = kt + 64;
            const int sn = (ti + 1) & 1;
            #pragma unroll
            for (int i = 0; i < 4; i++) {
                int ch = tid + i * 256;
                int r = ch >> 4, c = ch & 15;
                CP_ASYNC16(sb + AK_OFF2 + r * 256 + ((c ^ (r & 7)) << 4),
                           g_kfh + (size_t)(kn + r) * D_ + h * HD_ + c * 8);
            }
            #pragma unroll
            for (int i = 0; i < 4; i++) {
                int ch = tid + i * 256;
                int r = ch >> 3, c = ch & 7;
                uint32_t so = r * 128 + ((c ^ (r & 7)) << 4);
                CP_ASYNC16(sb + AV2(sn) + so,
                           g_vft + vbase + (size_t)r * T_ + kn + c * 8);
            }
            CP_COMMIT();
        }

        // ---- add mask ----
        #pragma unroll
        for (int nf = 0; nf < 8; nf++) {
            __nv_bfloat162 b0 = *reinterpret_cast<__nv_bfloat162*>(&mfr[nf]);
            __nv_bfloat162 b1 = *reinterpret_cast<__nv_bfloat162*>(&mfr[8 + nf]);
            s[nf][0] += __low2float(b0);
            s[nf][1] += __high2float(b0);
            s[nf][2] += __low2float(b1);
            s[nf][3] += __high2float(b1);
        }

        // ---- online softmax (rows row0, row0+8) ----
        float mx0 = s[0][0], mx1 = s[0][2];
        #pragma unroll
        for (int nf = 0; nf < 8; nf++) {
            mx0 = fmaxf(mx0, fmaxf(s[nf][0], s[nf][1]));
            mx1 = fmaxf(mx1, fmaxf(s[nf][2], s[nf][3]));
        }
        mx0 = fmaxf(mx0, __shfl_xor_sync(0xffffffffu, mx0, 1));
        mx0 = fmaxf(mx0, __shfl_xor_sync(0xffffffffu, mx0, 2));
        mx1 = fmaxf(mx1, __shfl_xor_sync(0xffffffffu, mx1, 1));
        mx1 = fmaxf(mx1, __shfl_xor_sync(0xffffffffu, mx1, 2));
        float mn0 = fmaxf(m0, mx0), mn1 = fmaxf(m1, mx1);
        float c0 = __expf(m0 - mn0), c1 = __expf(m1 - mn1);
        m0 = mn0; m1 = mn1;
        float sum0 = 0.f, sum1 = 0.f;
        #pragma unroll
        for (int nf = 0; nf < 8; nf++) {
            s[nf][0] = __expf(s[nf][0] - mn0);
            s[nf][1] = __expf(s[nf][1] - mn0);
            s[nf][2] = __expf(s[nf][2] - mn1);
            s[nf][3] = __expf(s[nf][3] - mn1);
            sum0 += s[nf][0] + s[nf][1];
            sum1 += s[nf][2] + s[nf][3];
        }
        sum0 += __shfl_xor_sync(0xffffffffu, sum0, 1);
        sum0 += __shfl_xor_sync(0xffffffffu, sum0, 2);
        sum1 += __shfl_xor_sync(0xffffffffu, sum1, 1);
        sum1 += __shfl_xor_sync(0xffffffffu, sum1, 2);
        l0 = l0 * c0 + sum0;
        l1 = l1 * c1 + sum1;
        #pragma unroll
        for (int nf = 0; nf < 16; nf++) {
            o[nf][0] *= c0; o[nf][1] *= c0;
            o[nf][2] *= c1; o[nf][3] *= c1;
        }

        // ---- O += P V (single fp16 product) from V stage ti&1 ----
        const uint32_t v_base = sb + AV2(ti & 1);
        #pragma unroll
        for (int j = 0; j < 4; j++) {
            uint32_t ph[4];
            #pragma unroll
            for (int u = 0; u < 2; u++) {
                __half2 hab = __floats2half2_rn(s[2 * j + u][0], s[2 * j + u][1]);
                __half2 hcd = __floats2half2_rn(s[2 * j + u][2], s[2 * j + u][3]);
                ph[2 * u]     = *reinterpret_cast<unsigned*>(&hab);
                ph[2 * u + 1] = *reinterpret_cast<unsigned*>(&hcd);
            }
            int cb = j * 2 + lhi;
            #pragma unroll
            for (int n2 = 0; n2 < 8; n2++) {
                uint32_t vh[4];
                int r = n2 * 16 + lm;
                ldsm4(vh, v_base + r * 128 + ((cb ^ (r & 7)) << 4));
                mma16816h(o[2 * n2],     ph, vh[0], vh[2]);
                mma16816h(o[2 * n2 + 1], ph, vh[1], vh[3]);
            }
        }

        if (ti + 1 < NT_) {
            CP_WAIT0();
            __syncthreads();
        }
    }

    // ---- epilogue: normalize + bf16 hi/lo split directly ----
    float inv0 = 1.f / l0, inv1 = 1.f / l1;
    size_t base0 = (size_t)row0 * D_ + h * HD_ + q4 * 2;
    size_t base1 = base0 + (size_t)8 * D_;
    #pragma unroll
    for (int nf = 0; nf < 16; nf++) {
        float a = o[nf][0] * inv0, b = o[nf][1] * inv0;
        __nv_bfloat162 hb = __floats2bfloat162_rn(a, b);
        __nv_bfloat162 lb = __floats2bfloat162_rn(
            a - __low2float(hb), b - __high2float(hb));
        *(uint32_t*)(g_aoh + base0 + nf * 8) = *reinterpret_cast<unsigned*>(&hb);
        *(uint32_t*)(g_aol + base0 + nf * 8) = *reinterpret_cast<unsigned*>(&lb);
        float cme = o[nf][2] * inv1, d = o[nf][3] * inv1;
        __nv_bfloat162 hb1 = __floats2bfloat162_rn(cme, d);
        __nv_bfloat162 lb1 = __floats2bfloat162_rn(
            cme - __low2float(hb1), d - __high2float(hb1));
        *(uint32_t*)(g_aoh + base1 + nf * 8) = *reinterpret_cast<unsigned*>(&hb1);
        *(uint32_t*)(g_aol + base1 + nf * 8) = *reinterpret_cast<unsigned*>(&lb1);
    }
}

// =================================================================
// Launch
// =================================================================
extern "C" void kernel_launch(void* const* d_in, const int* in_sizes, int n_in,
                              void* d_out, int out_size)
{
    const float* x    = (const float*)d_in[0];
    const float* mask = (const float*)d_in[1];
    const float* Wqkv = (const float*)d_in[2];
    const float* Wout = (const float*)d_in[3];
    float* out = (float*)d_out;

    float* qkv;
    __nv_bfloat16 *xh, *xl, *wqh, *wql, *woh, *wol, *aoh, *aol;
    cudaGetSymbolAddress((void**)&qkv, g_qkv);
    cudaGetSymbolAddress((void**)&xh,  g_xh);
    cudaGetSymbolAddress((void**)&xl,  g_xl);
    cudaGetSymbolAddress((void**)&wqh, g_wqh);
    cudaGetSymbolAddress((void**)&wql, g_wql);
    cudaGetSymbolAddress((void**)&woh, g_woh);
    cudaGetSymbolAddress((void**)&wol, g_wol);
    cudaGetSymbolAddress((void**)&aoh, g_aoh);
    cudaGetSymbolAddress((void**)&aol, g_aol);

    cudaFuncSetAttribute(gemm_split,
                         cudaFuncAttributeMaxDynamicSharedMemorySize, GEMM_SMEM);
    cudaFuncSetAttribute(attn2,
                         cudaFuncAttributeMaxDynamicSharedMemorySize, ATTN2_SMEM);

    // 1) split x / weights; mask -> bf16
    split_hl<<<(T_ * D_ / 4) / 256, 256>>>((const float4*)x, (uint2*)xh, (uint2*)xl);
    tsplit<<<dim3(TD3 / 32, D_ / 32), dim3(32, 8)>>>(Wqkv, wqh, wql, D_, TD3);
    tsplit<<<dim3(D_ / 32,  D_ / 32), dim3(32, 8)>>>(Wout, woh, wol, D_, D_);
    mask2bf<<<(T_ * (size_t)T_ / 4) / 256, 256>>>((const float4*)mask);

    // 2) qkv = x @ W_qkv
    gemm_split<<<dim3(TD3 / BN, T_ / BM), 256, GEMM_SMEM>>>(
        xh, xl, wqh, wql, qkv, T_, TD3, D_);

    // 3) normalize q (scale folded), k -> fp16; transpose V -> fp16
    l2norm_qk<<<(T_ * H_ * 2) / 8, 256>>>();
    vtsplit<<<dim3(T_ / 32, HD_ / 32, H_), dim3(32, 8)>>>();

    // 4) pipelined fp16 tensor-core flash attention -> g_aoh/g_aol
    attn2<<<dim3(H_, T_ / 128), 256, ATTN2_SMEM>>>();

    // 5) out = ao @ W_out
    gemm_split<<<dim3(D_ / BN, T_ / BM), 256, GEMM_SMEM>>>(
        aoh, aol, woh, wol, out, T_, D_, D_);
}

// round 8
// speedup vs baseline: 3.8495x; 1.0344x over previous
#include <cuda_runtime.h>
#include <cuda_bf16.h>
#include <cuda_fp16.h>
#include <math.h>
#include <stdint.h>

#define T_   4096
#define D_   2048
#define H_   16
#define HD_  128
#define TD3  6144   // 3*D

// ---------------- scratch (no allocations allowed) ----------------
__device__ float g_qkv[(size_t)T_ * TD3];   // [q | k | v] per row, fp32

// split-precision bf16 buffers for dense GEMMs
__device__ __nv_bfloat16 g_xh[(size_t)T_ * D_];
__device__ __nv_bfloat16 g_xl[(size_t)T_ * D_];
__device__ __nv_bfloat16 g_wqh[(size_t)TD3 * D_];   // Wqkv^T  [6144][2048]
__device__ __nv_bfloat16 g_wql[(size_t)TD3 * D_];
__device__ __nv_bfloat16 g_woh[(size_t)D_ * D_];    // Wout^T  [2048][2048]
__device__ __nv_bfloat16 g_wol[(size_t)D_ * D_];
__device__ __nv_bfloat16 g_aoh[(size_t)T_ * D_];
__device__ __nv_bfloat16 g_aol[(size_t)T_ * D_];

// attention fp16 operands
__device__ __half g_qfh[(size_t)T_ * D_];          // normalized q*scale*log2e, fp16
__device__ __half g_kfh[(size_t)T_ * D_];          // normalized k, fp16
__device__ __half g_vft[(size_t)H_ * HD_ * T_];    // V^T per head, fp16
__device__ __nv_bfloat16 g_maskb[(size_t)T_ * T_]; // mask * log2e, bf16

// =================================================================
// PTX helpers (portable: ldmatrix / mma.sync / cp.async)
// =================================================================
__device__ __forceinline__ uint32_t smem_u32(const void* p) {
    uint32_t a;
    asm("{ .reg .u64 t; cvta.to.shared.u64 t, %1; cvt.u32.u64 %0, t; }"
        : "=r"(a) : "l"(p));
    return a;
}
__device__ __forceinline__ void ldsm4(uint32_t* r, uint32_t a) {
    asm volatile("ldmatrix.sync.aligned.m8n8.x4.shared.b16 {%0,%1,%2,%3}, [%4];"
                 : "=r"(r[0]), "=r"(r[1]), "=r"(r[2]), "=r"(r[3]) : "r"(a));
}
__device__ __forceinline__ void mma16816(float* c, const uint32_t* a,
                                         uint32_t b0, uint32_t b1) {
    asm volatile(
        "mma.sync.aligned.m16n8k16.row.col.f32.bf16.bf16.f32 "
        "{%0,%1,%2,%3}, {%4,%5,%6,%7}, {%8,%9}, {%0,%1,%2,%3};"
        : "+f"(c[0]), "+f"(c[1]), "+f"(c[2]), "+f"(c[3])
        : "r"(a[0]), "r"(a[1]), "r"(a[2]), "r"(a[3]), "r"(b0), "r"(b1));
}
__device__ __forceinline__ void mma16816h(float* c, const uint32_t* a,
                                          uint32_t b0, uint32_t b1) {
    asm volatile(
        "mma.sync.aligned.m16n8k16.row.col.f32.f16.f16.f32 "
        "{%0,%1,%2,%3}, {%4,%5,%6,%7}, {%8,%9}, {%0,%1,%2,%3};"
        : "+f"(c[0]), "+f"(c[1]), "+f"(c[2]), "+f"(c[3])
        : "r"(a[0]), "r"(a[1]), "r"(a[2]), "r"(a[3]), "r"(b0), "r"(b1));
}
__device__ __forceinline__ uint32_t ex2h2(uint32_t x) {
    uint32_t r;
    asm("ex2.approx.f16x2 %0, %1;" : "=r"(r) : "r"(x));
    return r;
}
#define CP_ASYNC16(sa, ga) \
    asm volatile("cp.async.cg.shared.global [%0], [%1], 16;" :: "r"(sa), "l"(ga))
#define CP_COMMIT() asm volatile("cp.async.commit_group;" ::: "memory")
#define CP_WAIT0()  asm volatile("cp.async.wait_group 0;" ::: "memory")

#define LOG2E 1.4426950408889634f

// =================================================================
// Split / transpose / convert kernels
// =================================================================
__global__ __launch_bounds__(256) void split_hl(const float4* __restrict__ src,
                                                uint2* __restrict__ hi,
                                                uint2* __restrict__ lo)
{
    size_t i = (size_t)blockIdx.x * 256 + threadIdx.x;
    float4 v = src[i];
    __nv_bfloat162 h0 = __floats2bfloat162_rn(v.x, v.y);
    __nv_bfloat162 h1 = __floats2bfloat162_rn(v.z, v.w);
    float rx = v.x - __low2float(h0),  ry = v.y - __high2float(h0);
    float rz = v.z - __low2float(h1),  rw = v.w - __high2float(h1);
    __nv_bfloat162 l0 = __floats2bfloat162_rn(rx, ry);
    __nv_bfloat162 l1 = __floats2bfloat162_rn(rz, rw);
    uint2 hv, lv;
    hv.x = *reinterpret_cast<unsigned*>(&h0); hv.y = *reinterpret_cast<unsigned*>(&h1);
    lv.x = *reinterpret_cast<unsigned*>(&l0); lv.y = *reinterpret_cast<unsigned*>(&l1);
    hi[i] = hv;
    lo[i] = lv;
}

// mask * log2e -> bf16 (prepared for base-2 exp)
__global__ __launch_bounds__(256) void mask2bf(const float4* __restrict__ m)
{
    size_t i = (size_t)blockIdx.x * 256 + threadIdx.x;
    float4 v = m[i];
    __nv_bfloat162 a = __floats2bfloat162_rn(v.x * LOG2E, v.y * LOG2E);
    __nv_bfloat162 b = __floats2bfloat162_rn(v.z * LOG2E, v.w * LOG2E);
    uint2 o;
    o.x = *reinterpret_cast<unsigned*>(&a);
    o.y = *reinterpret_cast<unsigned*>(&b);
    ((uint2*)g_maskb)[i] = o;
}

// src[R][C] fp32  ->  out[C][R] bf16 hi/lo (transpose + split)
__global__ __launch_bounds__(256) void tsplit(const float* __restrict__ src,
                                              __nv_bfloat16* __restrict__ dh,
                                              __nv_bfloat16* __restrict__ dl,
                                              int R, int C)
{
    __shared__ float tile[32][33];
    int tx = threadIdx.x, ty = threadIdx.y;
    int x0 = blockIdx.x * 32, y0 = blockIdx.y * 32;
    #pragma unroll
    for (int j = 0; j < 4; j++)
        tile[ty + j * 8][tx] = src[(size_t)(y0 + ty + j * 8) * C + x0 + tx];
    __syncthreads();
    #pragma unroll
    for (int j = 0; j < 4; j++) {
        float v = tile[tx][ty + j * 8];
        __nv_bfloat16 h = __float2bfloat16(v);
        __nv_bfloat16 l = __float2bfloat16(v - __bfloat162float(h));
        size_t o = (size_t)(x0 + ty + j * 8) * R + y0 + tx;
        dh[o] = h;
        dl[o] = l;
    }
}

// V region of g_qkv -> per-head transposed fp16: g_vft[h][d][t]
__global__ __launch_bounds__(256) void vtsplit()
{
    __shared__ float tile[32][33];
    int tx = threadIdx.x, ty = threadIdx.y;
    int t0 = blockIdx.x * 32, d0 = blockIdx.y * 32, h = blockIdx.z;
    #pragma unroll
    for (int j = 0; j < 4; j++)
        tile[ty + j * 8][tx] =
            g_qkv[(size_t)(t0 + ty + j * 8) * TD3 + 2 * D_ + h * HD_ + d0 + tx];
    __syncthreads();
    size_t base = (size_t)h * HD_ * T_;
    #pragma unroll
    for (int j = 0; j < 4; j++) {
        float v = tile[tx][ty + j * 8];
        size_t o = base + (size_t)(d0 + ty + j * 8) * T_ + t0 + tx;
        g_vft[o] = __float2half(v);
    }
}

// =================================================================
// Split-bf16 mma.sync GEMM (unchanged — passing, tensor=52.8%)
// =================================================================
#define BM 128
#define BN 128
#define BKC 32
#define ROWB 80
#define TILE_B (128 * ROWB)
#define STAGE_B (4 * TILE_B)
#define GEMM_SMEM (2 * STAGE_B)

__device__ __forceinline__ void cpa_tile(uint32_t sbase,
                                         const __nv_bfloat16* __restrict__ g,
                                         int row0, int k0, int K, int tid)
{
    #pragma unroll
    for (int i = 0; i < 2; i++) {
        int ch = tid + i * 256;
        int r  = ch >> 2;
        int cc = (ch & 3) * 8;
        uint32_t sa = sbase + r * ROWB + cc * 2;
        const void* ga = g + (size_t)(row0 + r) * K + k0 + cc;
        CP_ASYNC16(sa, ga);
    }
}

__global__ __launch_bounds__(256) void gemm_split(
    const __nv_bfloat16* __restrict__ Ah, const __nv_bfloat16* __restrict__ Al,
    const __nv_bfloat16* __restrict__ Bh, const __nv_bfloat16* __restrict__ Bl,
    float* __restrict__ C, int M, int N, int K)
{
    extern __shared__ char smem[];
    uint32_t sb = smem_u32(smem);
    const int tid  = threadIdx.x;
    const int lane = tid & 31;
    const int wid  = tid >> 5;
    const int wm   = wid >> 2;
    const int wn   = wid & 3;
    const int m0 = blockIdx.y * BM;
    const int n0 = blockIdx.x * BN;
    const int NC = K / BKC;

    float acc[4][4][4] = {};

    cpa_tile(sb,              Ah, m0, 0, K, tid);
    cpa_tile(sb + TILE_B,     Al, m0, 0, K, tid);
    cpa_tile(sb + 2 * TILE_B, Bh, n0, 0, K, tid);
    cpa_tile(sb + 3 * TILE_B, Bl, n0, 0, K, tid);
    CP_COMMIT();
    CP_WAIT0();
    __syncthreads();

    const int lm  = lane & 15;
    const int lk8 = (lane >> 4) * 8;

    for (int c = 0; c < NC; c++) {
        uint32_t sbuf = sb + (c & 1) * STAGE_B;
        if (c + 1 < NC) {
            uint32_t snext = sb + ((c + 1) & 1) * STAGE_B;
            int k0 = (c + 1) * BKC;
            cpa_tile(snext,              Ah, m0, k0, K, tid);
            cpa_tile(snext + TILE_B,     Al, m0, k0, K, tid);
            cpa_tile(snext + 2 * TILE_B, Bh, n0, k0, K, tid);
            cpa_tile(snext + 3 * TILE_B, Bl, n0, k0, K, tid);
            CP_COMMIT();
        }

        uint32_t sA  = sbuf;
        uint32_t sAl = sbuf + TILE_B;
        uint32_t sB  = sbuf + 2 * TILE_B;
        uint32_t sBl = sbuf + 3 * TILE_B;

        #pragma unroll
        for (int ks = 0; ks < 2; ks++) {
            uint32_t kb = (ks * 16 + lk8) * 2;
            uint32_t ah[4][4], al[4][4], bh[2][4], bl[2][4];
            #pragma unroll
            for (int mf = 0; mf < 4; mf++) {
                uint32_t ro = (wm * 64 + mf * 16 + lm) * ROWB + kb;
                ldsm4(ah[mf], sA + ro);
                ldsm4(al[mf], sAl + ro);
            }
            #pragma unroll
            for (int nf2 = 0; nf2 < 2; nf2++) {
                uint32_t ro = (wn * 32 + nf2 * 16 + lm) * ROWB + kb;
                ldsm4(bh[nf2], sB + ro);
                ldsm4(bl[nf2], sBl + ro);
            }
            #pragma unroll
            for (int mf = 0; mf < 4; mf++)
                #pragma unroll
                for (int nf = 0; nf < 4; nf++) {
                    uint32_t b0h = bh[nf >> 1][nf & 1];
                    uint32_t b1h = bh[nf >> 1][(nf & 1) + 2];
                    uint32_t b0l = bl[nf >> 1][nf & 1];
                    uint32_t b1l = bl[nf >> 1][(nf & 1) + 2];
                    mma16816(acc[mf][nf], ah[mf], b0h, b1h);
                    mma16816(acc[mf][nf], ah[mf], b0l, b1l);
                    mma16816(acc[mf][nf], al[mf], b0h, b1h);
                }
        }

        if (c + 1 < NC) {
            CP_WAIT0();
            __syncthreads();
        }
    }

    int mbase = m0 + wm * 64;
    int nbase = n0 + wn * 32;
    #pragma unroll
    for (int mf = 0; mf < 4; mf++)
        #pragma unroll
        for (int nf = 0; nf < 4; nf++) {
            int r0 = mbase + mf * 16 + (lane >> 2);
            int c0 = nbase + nf * 8 + (lane & 3) * 2;
            *(float2*)&C[(size_t)r0 * N + c0] =
                make_float2(acc[mf][nf][0], acc[mf][nf][1]);
            *(float2*)&C[(size_t)(r0 + 8) * N + c0] =
                make_float2(acc[mf][nf][2], acc[mf][nf][3]);
        }
}

// =================================================================
// L2-normalize q,k -> fp16 (softmax scale * log2e folded into q).
// =================================================================
__global__ __launch_bounds__(256) void l2norm_qk()
{
    int gw = blockIdx.x * 8 + (threadIdx.x >> 5);
    int l  = threadIdx.x & 31;
    int which = gw >> 16;           // 0 = q, 1 = k
    int rem   = gw & 65535;
    int t = rem >> 4;
    int h = rem & 15;

    const float* p = g_qkv + (size_t)t * TD3 + which * D_ + h * HD_ + l * 4;
    float4 v = *(const float4*)p;
    float ss = v.x * v.x + v.y * v.y + v.z * v.z + v.w * v.w;
    #pragma unroll
    for (int o = 16; o; o >>= 1) ss += __shfl_xor_sync(0xffffffffu, ss, o);
    // q: fold 128^-0.5 * log2(e) so S accumulators are base-2 exponents
    float sc = which ? 1.0f : (0.08838834764831845f * LOG2E);
    float inv = sc / fmaxf(sqrtf(ss), 1e-12f);
    __half2 h0 = __floats2half2_rn(v.x * inv, v.y * inv);
    __half2 h1 = __floats2half2_rn(v.z * inv, v.w * inv);
    uint2 hv;
    hv.x = *reinterpret_cast<unsigned*>(&h0);
    hv.y = *reinterpret_cast<unsigned*>(&h1);
    __half* dst = which ? g_kfh : g_qfh;
    *(uint2*)(dst + (size_t)t * D_ + h * HD_ + l * 4) = hv;
}

// =================================================================
// Tensor-core flash attention, fp16, no-max softmax (bounded logits),
// exp via ex2.approx.f16x2, row-sum via ones-MMA.
// grid (H, T/128), 256 thr (8 warps), warp w owns q-rows 16w..16w+15.
// =================================================================
#define AQ_OFF2 0
#define AK_OFF2 32768
#define AV2(s)  (49152 + (s) * 16384)
#define ATTN2_SMEM 81920
#define NT_ (T_ / 64)

__global__ __launch_bounds__(256, 2) void attn2()
{
    extern __shared__ char sm2[];
    uint32_t sb = smem_u32(sm2);
    const int tid = threadIdx.x, lane = tid & 31, w = tid >> 5;
    const int g = lane >> 2, q4 = lane & 3;
    const int lm = lane & 15, lhi = lane >> 4;
    const int h = blockIdx.x, q0 = blockIdx.y * 128;
    const uint32_t ONES2 = 0x3C003C00u;   // half2(1,1)

    const size_t vbase = (size_t)h * HD_ * T_;

    // ---- prologue: Q + K(0) + V(0) ----
    #pragma unroll
    for (int i = 0; i < 8; i++) {
        int ch = tid + i * 256;
        int r = ch >> 4, c = ch & 15;
        CP_ASYNC16(sb + AQ_OFF2 + r * 256 + ((c ^ (r & 7)) << 4),
                   g_qfh + (size_t)(q0 + r) * D_ + h * HD_ + c * 8);
    }
    #pragma unroll
    for (int i = 0; i < 4; i++) {
        int ch = tid + i * 256;
        int r = ch >> 4, c = ch & 15;
        CP_ASYNC16(sb + AK_OFF2 + r * 256 + ((c ^ (r & 7)) << 4),
                   g_kfh + (size_t)r * D_ + h * HD_ + c * 8);
    }
    #pragma unroll
    for (int i = 0; i < 4; i++) {
        int ch = tid + i * 256;
        int r = ch >> 3, c = ch & 7;
        uint32_t so = r * 128 + ((c ^ (r & 7)) << 4);
        CP_ASYNC16(sb + AV2(0) + so, g_vft + vbase + (size_t)r * T_ + c * 8);
    }
    CP_COMMIT();

    float o[16][4] = {};
    float lsum[4] = {};     // [0]: row sum (row0), [2]: row sum (row0+8)
    const int row0 = q0 + w * 16 + g;

    CP_WAIT0();
    __syncthreads();

    for (int ti = 0; ti < NT_; ti++) {
        const int kt = ti * 64;

        // ---- mask prefetch (bf16x2, pre-scaled by log2e) ----
        uint32_t mfr[16];
        {
            const __nv_bfloat16* mb0 = g_maskb + (size_t)row0 * T_ + kt + q4 * 2;
            #pragma unroll
            for (int nf = 0; nf < 8; nf++) {
                mfr[nf]     = *(const uint32_t*)(mb0 + nf * 8);
                mfr[8 + nf] = *(const uint32_t*)(mb0 + 8 * T_ + nf * 8);
            }
        }

        // ---- S = Q K^T (scale*log2e pre-folded into q), fp16 ----
        float s[8][4] = {};
        #pragma unroll
        for (int ks = 0; ks < 8; ks++) {
            int cb = ks * 2 + lhi;
            uint32_t aq[4];
            {
                int r = w * 16 + lm;
                ldsm4(aq, sb + AQ_OFF2 + r * 256 + ((cb ^ (r & 7)) << 4));
            }
            #pragma unroll
            for (int n2 = 0; n2 < 4; n2++) {
                uint32_t kf[4];
                int r = n2 * 16 + lm;
                ldsm4(kf, sb + AK_OFF2 + r * 256 + ((cb ^ (r & 7)) << 4));
                mma16816h(s[2 * n2],     aq, kf[0], kf[2]);
                mma16816h(s[2 * n2 + 1], aq, kf[1], kf[3]);
            }
        }

        __syncthreads();   // all warps done reading K(ti)

        // ---- issue K(ti+1), V(ti+1): overlap exp + PV ----
        if (ti + 1 < NT_) {
            const int kn = kt + 64;
            const int sn = (ti + 1) & 1;
            #pragma unroll
            for (int i = 0; i < 4; i++) {
                int ch = tid + i * 256;
                int r = ch >> 4, c = ch & 15;
                CP_ASYNC16(sb + AK_OFF2 + r * 256 + ((c ^ (r & 7)) << 4),
                           g_kfh + (size_t)(kn + r) * D_ + h * HD_ + c * 8);
            }
            #pragma unroll
            for (int i = 0; i < 4; i++) {
                int ch = tid + i * 256;
                int r = ch >> 3, c = ch & 7;
                uint32_t so = r * 128 + ((c ^ (r & 7)) << 4);
                CP_ASYNC16(sb + AV2(sn) + so,
                           g_vft + vbase + (size_t)r * T_ + kn + c * 8);
            }
            CP_COMMIT();
        }

        // ---- add mask (already *log2e) ----
        #pragma unroll
        for (int nf = 0; nf < 8; nf++) {
            __nv_bfloat162 b0 = *reinterpret_cast<__nv_bfloat162*>(&mfr[nf]);
            __nv_bfloat162 b1 = *reinterpret_cast<__nv_bfloat162*>(&mfr[8 + nf]);
            s[nf][0] += __low2float(b0);
            s[nf][1] += __high2float(b0);
            s[nf][2] += __low2float(b1);
            s[nf][3] += __high2float(b1);
        }

        // ---- P = 2^S (fp16x2), row-sum via ones-MMA, O += P V ----
        const uint32_t v_base = sb + AV2(ti & 1);
        #pragma unroll
        for (int j = 0; j < 4; j++) {
            uint32_t ph[4];
            #pragma unroll
            for (int u = 0; u < 2; u++) {
                int idx = 2 * j + u;
                __half2 hab = __floats2half2_rn(s[idx][0], s[idx][1]);
                __half2 hcd = __floats2half2_rn(s[idx][2], s[idx][3]);
                ph[2 * u]     = ex2h2(*reinterpret_cast<unsigned*>(&hab));
                ph[2 * u + 1] = ex2h2(*reinterpret_cast<unsigned*>(&hcd));
            }
            // row sums: P (16x16) x ones(16x8) accumulated into lsum
            mma16816h(lsum, ph, ONES2, ONES2);

            int cb = j * 2 + lhi;
            #pragma unroll
            for (int n2 = 0; n2 < 8; n2++) {
                uint32_t vh[4];
                int r = n2 * 16 + lm;
                ldsm4(vh, v_base + r * 128 + ((cb ^ (r & 7)) << 4));
                mma16816h(o[2 * n2],     ph, vh[0], vh[2]);
                mma16816h(o[2 * n2 + 1], ph, vh[1], vh[3]);
            }
        }

        if (ti + 1 < NT_) {
            CP_WAIT0();
            __syncthreads();
        }
    }

    // ---- epilogue: normalize by ones-MMA row sums + bf16 hi/lo split ----
    float inv0 = 1.f / lsum[0], inv1 = 1.f / lsum[2];
    size_t base0 = (size_t)row0 * D_ + h * HD_ + q4 * 2;
    size_t base1 = base0 + (size_t)8 * D_;
    #pragma unroll
    for (int nf = 0; nf < 16; nf++) {
        float a = o[nf][0] * inv0, b = o[nf][1] * inv0;
        __nv_bfloat162 hb = __floats2bfloat162_rn(a, b);
        __nv_bfloat162 lb = __floats2bfloat162_rn(
            a - __low2float(hb), b - __high2float(hb));
        *(uint32_t*)(g_aoh + base0 + nf * 8) = *reinterpret_cast<unsigned*>(&hb);
        *(uint32_t*)(g_aol + base0 + nf * 8) = *reinterpret_cast<unsigned*>(&lb);
        float cme = o[nf][2] * inv1, d = o[nf][3] * inv1;
        __nv_bfloat162 hb1 = __floats2bfloat162_rn(cme, d);
        __nv_bfloat162 lb1 = __floats2bfloat162_rn(
            cme - __low2float(hb1), d - __high2float(hb1));
        *(uint32_t*)(g_aoh + base1 + nf * 8) = *reinterpret_cast<unsigned*>(&hb1);
        *(uint32_t*)(g_aol + base1 + nf * 8) = *reinterpret_cast<unsigned*>(&lb1);
    }
}

// =================================================================
// Launch
// =================================================================
extern "C" void kernel_launch(void* const* d_in, const int* in_sizes, int n_in,
                              void* d_out, int out_size)
{
    const float* x    = (const float*)d_in[0];
    const float* mask = (const float*)d_in[1];
    const float* Wqkv = (const float*)d_in[2];
    const float* Wout = (const float*)d_in[3];
    float* out = (float*)d_out;

    float* qkv;
    __nv_bfloat16 *xh, *xl, *wqh, *wql, *woh, *wol, *aoh, *aol;
    cudaGetSymbolAddress((void**)&qkv, g_qkv);
    cudaGetSymbolAddress((void**)&xh,  g_xh);
    cudaGetSymbolAddress((void**)&xl,  g_xl);
    cudaGetSymbolAddress((void**)&wqh, g_wqh);
    cudaGetSymbolAddress((void**)&wql, g_wql);
    cudaGetSymbolAddress((void**)&woh, g_woh);
    cudaGetSymbolAddress((void**)&wol, g_wol);
    cudaGetSymbolAddress((void**)&aoh, g_aoh);
    cudaGetSymbolAddress((void**)&aol, g_aol);

    cudaFuncSetAttribute(gemm_split,
                         cudaFuncAttributeMaxDynamicSharedMemorySize, GEMM_SMEM);
    cudaFuncSetAttribute(attn2,
                         cudaFuncAttributeMaxDynamicSharedMemorySize, ATTN2_SMEM);

    // 1) split x / weights; mask*log2e -> bf16
    split_hl<<<(T_ * D_ / 4) / 256, 256>>>((const float4*)x, (uint2*)xh, (uint2*)xl);
    tsplit<<<dim3(TD3 / 32, D_ / 32), dim3(32, 8)>>>(Wqkv, wqh, wql, D_, TD3);
    tsplit<<<dim3(D_ / 32,  D_ / 32), dim3(32, 8)>>>(Wout, woh, wol, D_, D_);
    mask2bf<<<(T_ * (size_t)T_ / 4) / 256, 256>>>((const float4*)mask);

    // 2) qkv = x @ W_qkv
    gemm_split<<<dim3(TD3 / BN, T_ / BM), 256, GEMM_SMEM>>>(
        xh, xl, wqh, wql, qkv, T_, TD3, D_);

    // 3) normalize q (scale*log2e folded), k -> fp16; transpose V -> fp16
    l2norm_qk<<<(T_ * H_ * 2) / 8, 256>>>();
    vtsplit<<<dim3(T_ / 32, HD_ / 32, H_), dim3(32, 8)>>>();

    // 4) fp16 flash attention (no-max softmax, ex2.f16x2) -> g_aoh/g_aol
    attn2<<<dim3(H_, T_ / 128), 256, ATTN2_SMEM>>>();

    // 5) out = ao @ W_out
    gemm_split<<<dim3(D_ / BN, T_ / BM), 256, GEMM_SMEM>>>(
        aoh, aol, woh, wol, out, T_, D_, D_);
}